// round 4
// baseline (speedup 1.0000x reference)
#include <cuda_runtime.h>

#define SEQ   4096
#define DM    1024
#define NH    16
#define HD    64
#define WIN   256

// Scratch (allocation-free: __device__ globals)
__device__ float g_q[SEQ * DM];
__device__ float g_k[SEQ * DM];
__device__ float g_v[SEQ * DM];
__device__ float g_att[SEQ * DM];

// ---------------------------------------------------------------------------
// SGEMM with bias: C = A[M,K] @ B[K,N] + bias.  blockIdx.z selects (B, bias, C)
// so the three QKV projections run as one 768-CTA launch.
// Block tile 128x128, K-tile 16, 8x8 per thread, 256 threads.
// ---------------------------------------------------------------------------
#define BM 128
#define BN 128
#define BK 16
#define TM 8
#define TN 8

__global__ __launch_bounds__(256, 2)
void sgemm_bias(const float* __restrict__ A,
                const float* __restrict__ B0, const float* __restrict__ B1,
                const float* __restrict__ B2,
                const float* __restrict__ b0, const float* __restrict__ b1,
                const float* __restrict__ b2,
                float* __restrict__ C0, float* __restrict__ C1,
                float* __restrict__ C2,
                int M, int N, int K)
{
    const float* B    = (blockIdx.z == 0) ? B0 : ((blockIdx.z == 1) ? B1 : B2);
    const float* bias = (blockIdx.z == 0) ? b0 : ((blockIdx.z == 1) ? b1 : b2);
    float*       C    = (blockIdx.z == 0) ? C0 : ((blockIdx.z == 1) ? C1 : C2);

    __shared__ float As[BK][BM + 4];   // A tile transposed; +4 pad reduces store conflicts
    __shared__ float Bs[BK][BN];

    const int tid = threadIdx.x;
    const float* Aptr = A + (long)blockIdx.y * BM * K;
    const float* Bptr = B + blockIdx.x * BN;

    float acc[TM][TN];
#pragma unroll
    for (int i = 0; i < TM; i++)
#pragma unroll
        for (int j = 0; j < TN; j++) acc[i][j] = 0.f;

    const int rm = (tid >> 4) * TM;    // row offset within block tile
    const int rn = (tid & 15) * TN;    // col offset within block tile

    for (int kt = 0; kt < K; kt += BK) {
        // Load A tile (128x16) as float4 along K, store transposed.
#pragma unroll
        for (int i = 0; i < 2; i++) {
            int idx = tid + i * 256;
            int row = idx >> 2;
            int c4  = (idx & 3) * 4;
            float4 v = *(const float4*)(Aptr + (long)row * K + kt + c4);
            As[c4 + 0][row] = v.x;
            As[c4 + 1][row] = v.y;
            As[c4 + 2][row] = v.z;
            As[c4 + 3][row] = v.w;
        }
        // Load B tile (16x128) as float4, direct.
#pragma unroll
        for (int i = 0; i < 2; i++) {
            int idx = tid + i * 256;
            int row = idx >> 5;
            int c   = (idx & 31) * 4;
            *(float4*)&Bs[row][c] = *(const float4*)(Bptr + (long)(kt + row) * N + c);
        }
        __syncthreads();

#pragma unroll
        for (int kk = 0; kk < BK; kk++) {
            float a[TM], b[TN];
            *(float4*)&a[0] = *(float4*)&As[kk][rm];
            *(float4*)&a[4] = *(float4*)&As[kk][rm + 4];
            *(float4*)&b[0] = *(float4*)&Bs[kk][rn];
            *(float4*)&b[4] = *(float4*)&Bs[kk][rn + 4];
#pragma unroll
            for (int i = 0; i < TM; i++)
#pragma unroll
                for (int j = 0; j < TN; j++)
                    acc[i][j] += a[i] * b[j];
        }
        __syncthreads();
    }

    // Epilogue with bias, vectorized stores.
    const int row0 = blockIdx.y * BM + rm;
    const int col0 = blockIdx.x * BN + rn;
#pragma unroll
    for (int i = 0; i < TM; i++) {
#pragma unroll
        for (int j4 = 0; j4 < TN; j4 += 4) {
            float4 bv = *(const float4*)&bias[col0 + j4];
            float4 o;
            o.x = acc[i][j4 + 0] + bv.x;
            o.y = acc[i][j4 + 1] + bv.y;
            o.z = acc[i][j4 + 2] + bv.z;
            o.w = acc[i][j4 + 3] + bv.w;
            *(float4*)&C[(long)(row0 + i) * N + col0 + j4] = o;
        }
    }
}

// ---------------------------------------------------------------------------
// Sliding-window flash attention.
// Grid: (64 query tiles, 16 heads). 256 threads: row r = tid>>2 (0..63),
// column group cg = tid&3. Thread owns columns c = cg + 4*j (interleaved so the
// 4 column groups map to distinct SMEM banks for all inner-loop loads).
// SMEM strides of 68 floats (mult. of 4 for float4; 68 mod 32 = 4 gives
// conflict-free row-broadcast reads).
// Online softmax across the <=5 key tiles of the 256-wide causal window.
// ---------------------------------------------------------------------------
#define ATT_STRIDE 68
#define ATT_SMEM_FLOATS (4 * 64 * ATT_STRIDE)
#define ATT_SMEM_BYTES  (ATT_SMEM_FLOATS * 4)

__global__ __launch_bounds__(256, 2)
void attn_kernel()
{
    extern __shared__ float sm[];
    float* Qs = sm;                        // [64][68]  (Q * 1/sqrt(hd))
    float* Ps = Qs + 64 * ATT_STRIDE;      // [64][68]  probabilities
    float* Ks = Ps + 64 * ATT_STRIDE;      // [key][d]
    float* Vt = Ks + 64 * ATT_STRIDE;      // [d][key]  (transposed V)

    const int h   = blockIdx.y;
    const int qt  = blockIdx.x;
    const int q0  = qt * 64;
    const int tid = threadIdx.x;
    const int r   = tid >> 2;
    const int cg  = tid & 3;
    const int col = h * HD;

    // Load + scale Q tile
    for (int i = tid; i < 64 * 16; i += 256) {
        int row = i >> 4;
        int c4  = (i & 15) * 4;
        float4 v = *(const float4*)&g_q[(long)(q0 + row) * DM + col + c4];
        float* dst = &Qs[row * ATT_STRIDE + c4];
        dst[0] = v.x * 0.125f;
        dst[1] = v.y * 0.125f;
        dst[2] = v.z * 0.125f;
        dst[3] = v.w * 0.125f;
    }

    float m = -1e30f, l = 0.f;
    float o[16];
#pragma unroll
    for (int j = 0; j < 16; j++) o[j] = 0.f;

    const int kt0 = (qt >= 4) ? (qt - 4) : 0;
    for (int kt = kt0; kt <= qt; kt++) {
        __syncthreads();   // previous iteration done reading Ks/Vt/Ps
        // Load K tile [key][d]; load V transposed into Vt[d][key]
        for (int i = tid; i < 64 * 16; i += 256) {
            int row = i >> 4;
            int c4  = (i & 15) * 4;
            long gbase = (long)(kt * 64 + row) * DM + col + c4;
            *(float4*)&Ks[row * ATT_STRIDE + c4] = *(const float4*)&g_k[gbase];
            float4 vv = *(const float4*)&g_v[gbase];
            Vt[(c4 + 0) * ATT_STRIDE + row] = vv.x;
            Vt[(c4 + 1) * ATT_STRIDE + row] = vv.y;
            Vt[(c4 + 2) * ATT_STRIDE + row] = vv.z;
            Vt[(c4 + 3) * ATT_STRIDE + row] = vv.w;
        }
        __syncthreads();

        // S = Q K^T for this thread's 16 interleaved columns
        float s[16];
#pragma unroll
        for (int j = 0; j < 16; j++) s[j] = 0.f;
#pragma unroll 4
        for (int d4 = 0; d4 < 16; d4++) {
            float4 qv = *(float4*)&Qs[r * ATT_STRIDE + d4 * 4];
#pragma unroll
            for (int j = 0; j < 16; j++) {
                int c = cg + 4 * j;
                float4 kv = *(float4*)&Ks[c * ATT_STRIDE + d4 * 4];
                s[j] += qv.x * kv.x + qv.y * kv.y + qv.z * kv.z + qv.w * kv.w;
            }
        }

        // Causal sliding-window mask + tile max
        const int iq = q0 + r;
        float tmax = -1e30f;
#pragma unroll
        for (int j = 0; j < 16; j++) {
            int jg = kt * 64 + cg + 4 * j;
            bool ok = (jg <= iq) && (iq - jg < WIN);
            s[j] = ok ? s[j] : -1e30f;
            tmax = fmaxf(tmax, s[j]);
        }
        tmax = fmaxf(tmax, __shfl_xor_sync(0xffffffffu, tmax, 1));
        tmax = fmaxf(tmax, __shfl_xor_sync(0xffffffffu, tmax, 2));

        float mnew = fmaxf(m, tmax);
        float corr = __expf(m - mnew);
        m = mnew;

        float ls = 0.f;
#pragma unroll
        for (int j = 0; j < 16; j++) {
            float p = (s[j] > -1e29f) ? __expf(s[j] - m) : 0.f;
            Ps[r * ATT_STRIDE + cg + 4 * j] = p;
            ls += p;
        }
        ls += __shfl_xor_sync(0xffffffffu, ls, 1);
        ls += __shfl_xor_sync(0xffffffffu, ls, 2);
        l = l * corr + ls;
#pragma unroll
        for (int j = 0; j < 16; j++) o[j] *= corr;

        __syncthreads();   // Ps visible to the whole row group

        // O += P @ V   (Vt gives vectorized loads along the key axis)
#pragma unroll 4
        for (int k4 = 0; k4 < 16; k4++) {
            float4 pv = *(float4*)&Ps[r * ATT_STRIDE + k4 * 4];
#pragma unroll
            for (int j = 0; j < 16; j++) {
                int c = cg + 4 * j;
                float4 vv = *(float4*)&Vt[c * ATT_STRIDE + k4 * 4];
                o[j] += pv.x * vv.x + pv.y * vv.y + pv.z * vv.z + pv.w * vv.w;
            }
        }
    }

    const float inv = 1.f / l;
#pragma unroll
    for (int j = 0; j < 16; j++)
        g_att[(long)(q0 + r) * DM + col + cg + 4 * j] = o[j] * inv;
}

// ---------------------------------------------------------------------------
// Launch: QKV projections (one fused launch) -> attention -> output projection
// Input order resolved at runtime from in_sizes: weights are DM*DM elements,
// biases are DM. setup_inputs() inserts x, Wq, Wk, Wv, Wo, bq, bk, bv, bo
// (grouped); we also tolerate the interleaved (W,b) pair order.
// ---------------------------------------------------------------------------
extern "C" void kernel_launch(void* const* d_in, const int* in_sizes, int n_in,
                              void* d_out, int out_size)
{
    const float* x = (const float*)d_in[0];
    const float *Wq, *Wk, *Wv, *Wo, *bq, *bk, *bv, *bo;

    if (in_sizes[2] == DM) {
        // interleaved: x, Wq, bq, Wk, bk, Wv, bv, Wo, bo
        Wq = (const float*)d_in[1]; bq = (const float*)d_in[2];
        Wk = (const float*)d_in[3]; bk = (const float*)d_in[4];
        Wv = (const float*)d_in[5]; bv = (const float*)d_in[6];
        Wo = (const float*)d_in[7]; bo = (const float*)d_in[8];
    } else {
        // grouped (setup_inputs order): x, Wq, Wk, Wv, Wo, bq, bk, bv, bo
        Wq = (const float*)d_in[1]; Wk = (const float*)d_in[2];
        Wv = (const float*)d_in[3]; Wo = (const float*)d_in[4];
        bq = (const float*)d_in[5]; bk = (const float*)d_in[6];
        bv = (const float*)d_in[7]; bo = (const float*)d_in[8];
    }
    float* out = (float*)d_out;

    float *q, *k, *v, *att;
    cudaGetSymbolAddress((void**)&q,   g_q);
    cudaGetSymbolAddress((void**)&k,   g_k);
    cudaGetSymbolAddress((void**)&v,   g_v);
    cudaGetSymbolAddress((void**)&att, g_att);

    cudaFuncSetAttribute(attn_kernel,
                         cudaFuncAttributeMaxDynamicSharedMemorySize,
                         ATT_SMEM_BYTES);

    dim3 gqkv(DM / BN, SEQ / BM, 3);
    sgemm_bias<<<gqkv, 256>>>(x, Wq, Wk, Wv, bq, bk, bv, q, k, v,
                              SEQ, DM, DM);

    dim3 gat(SEQ / 64, NH);
    attn_kernel<<<gat, 256, ATT_SMEM_BYTES>>>();

    dim3 gout(DM / BN, SEQ / BM, 1);
    sgemm_bias<<<gout, 256>>>(att, Wo, Wo, Wo, bo, bo, bo, out, out, out,
                              SEQ, DM, DM);
}

// round 5
// speedup vs baseline: 1.7917x; 1.7917x over previous
#include <cuda_runtime.h>
#include <cstdint>

#define SEQ   4096
#define DM    1024
#define NH    16
#define HD    64
#define WIN   256

// Scratch (allocation-free: __device__ globals)
__device__ float g_q[SEQ * DM];
__device__ float g_k[SEQ * DM];
__device__ float g_v[SEQ * DM];
__device__ float g_att[SEQ * DM];

// ---------------------------------------------------------------------------
// tf32 tensor-core GEMM with bias: C = A[M,K] @ B[K,N] + bias.
// blockIdx.z selects (B, bias, C) so QKV runs as one 768-CTA launch.
// CTA tile 128x128x32, 8 warps, warp tile 64x32, mma.m16n8k8.tf32.
// SMEM: As[k][m] stride 137 (conflict-free stores, <=2-way frag loads),
//       Bs[k][n] stride 136 (conflict-free both ways).
// ---------------------------------------------------------------------------
#define GBM 128
#define GBN 128
#define GBK 32
#define SA  137
#define SB  136

__device__ __forceinline__ uint32_t f2tf(float f) {
    uint32_t u;
    asm("cvt.rna.tf32.f32 %0, %1;" : "=r"(u) : "f"(f));
    return u;
}

__device__ __forceinline__ void mma_tf32(float (&d)[4],
                                         const uint32_t (&a)[4],
                                         const uint32_t (&b)[2]) {
    asm volatile(
        "mma.sync.aligned.m16n8k8.row.col.f32.tf32.tf32.f32 "
        "{%0,%1,%2,%3}, {%4,%5,%6,%7}, {%8,%9}, {%0,%1,%2,%3};\n"
        : "+f"(d[0]), "+f"(d[1]), "+f"(d[2]), "+f"(d[3])
        : "r"(a[0]), "r"(a[1]), "r"(a[2]), "r"(a[3]),
          "r"(b[0]), "r"(b[1]));
}

__global__ __launch_bounds__(256, 2)
void gemm_tf32_bias(const float* __restrict__ A,
                    const float* __restrict__ B0, const float* __restrict__ B1,
                    const float* __restrict__ B2,
                    const float* __restrict__ b0, const float* __restrict__ b1,
                    const float* __restrict__ b2,
                    float* __restrict__ C0, float* __restrict__ C1,
                    float* __restrict__ C2,
                    int M, int N, int K)
{
    const float* B    = (blockIdx.z == 0) ? B0 : ((blockIdx.z == 1) ? B1 : B2);
    const float* bias = (blockIdx.z == 0) ? b0 : ((blockIdx.z == 1) ? b1 : b2);
    float*       C    = (blockIdx.z == 0) ? C0 : ((blockIdx.z == 1) ? C1 : C2);

    __shared__ uint32_t As[GBK * SA];
    __shared__ uint32_t Bs[GBK * SB];

    const int tid  = threadIdx.x;
    const int wid  = tid >> 5;
    const int lane = tid & 31;
    const int wm   = wid & 1;     // 0..1 : 64-row slab
    const int wn   = wid >> 1;    // 0..3 : 32-col slab
    const int gid  = lane >> 2;   // 0..7
    const int tig  = lane & 3;    // 0..3

    const float* Aptr = A + (long)blockIdx.y * GBM * K;
    const float* Bptr = B + blockIdx.x * GBN;

    float acc[4][4][4];
#pragma unroll
    for (int mi = 0; mi < 4; mi++)
#pragma unroll
        for (int ni = 0; ni < 4; ni++)
#pragma unroll
            for (int r = 0; r < 4; r++) acc[mi][ni][r] = 0.f;

    for (int kt = 0; kt < K; kt += GBK) {
        // A tile 128x32 -> As[k][m] (transposed), tf32-converted.
#pragma unroll
        for (int i = 0; i < 4; i++) {
            int idx = tid + i * 256;
            int row = idx >> 3;          // 0..127
            int c4  = (idx & 7) * 4;     // 0..28
            float4 v = *(const float4*)(Aptr + (long)row * K + kt + c4);
            As[(c4 + 0) * SA + row] = f2tf(v.x);
            As[(c4 + 1) * SA + row] = f2tf(v.y);
            As[(c4 + 2) * SA + row] = f2tf(v.z);
            As[(c4 + 3) * SA + row] = f2tf(v.w);
        }
        // B tile 32x128 -> Bs[k][n], tf32-converted.
#pragma unroll
        for (int i = 0; i < 4; i++) {
            int idx = tid + i * 256;
            int row = idx >> 5;          // 0..31 (k)
            int c4  = (idx & 31) * 4;    // 0..124 (n)
            float4 v = *(const float4*)(Bptr + (long)(kt + row) * N + c4);
            uint4 w;
            w.x = f2tf(v.x); w.y = f2tf(v.y); w.z = f2tf(v.z); w.w = f2tf(v.w);
            *(uint4*)&Bs[row * SB + c4] = w;
        }
        __syncthreads();

#pragma unroll
        for (int ks = 0; ks < 4; ks++) {
            const int kb = ks * 8;
            uint32_t a[4][4], b[4][2];
#pragma unroll
            for (int mi = 0; mi < 4; mi++) {
                int m = wm * 64 + mi * 16 + gid;
                a[mi][0] = As[(kb + tig) * SA + m];
                a[mi][1] = As[(kb + tig) * SA + m + 8];
                a[mi][2] = As[(kb + tig + 4) * SA + m];
                a[mi][3] = As[(kb + tig + 4) * SA + m + 8];
            }
#pragma unroll
            for (int ni = 0; ni < 4; ni++) {
                int n = wn * 32 + ni * 8 + gid;
                b[ni][0] = Bs[(kb + tig) * SB + n];
                b[ni][1] = Bs[(kb + tig + 4) * SB + n];
            }
#pragma unroll
            for (int mi = 0; mi < 4; mi++)
#pragma unroll
                for (int ni = 0; ni < 4; ni++)
                    mma_tf32(acc[mi][ni], a[mi], b[ni]);
        }
        __syncthreads();
    }

    // Epilogue: bias + store (float2 per accumulator pair).
    const int row_base = blockIdx.y * GBM + wm * 64;
    const int col_base = blockIdx.x * GBN + wn * 32;
#pragma unroll
    for (int mi = 0; mi < 4; mi++) {
#pragma unroll
        for (int ni = 0; ni < 4; ni++) {
            int r0 = row_base + mi * 16 + gid;
            int c  = col_base + ni * 8 + 2 * tig;
            float2 bv = *(const float2*)&bias[c];
            float2 o01, o23;
            o01.x = acc[mi][ni][0] + bv.x;
            o01.y = acc[mi][ni][1] + bv.y;
            o23.x = acc[mi][ni][2] + bv.x;
            o23.y = acc[mi][ni][3] + bv.y;
            *(float2*)&C[(long)r0 * N + c]       = o01;
            *(float2*)&C[(long)(r0 + 8) * N + c] = o23;
        }
    }
}

// ---------------------------------------------------------------------------
// Sliding-window flash attention (unchanged from the passing baseline).
// ---------------------------------------------------------------------------
#define ATT_STRIDE 68
#define ATT_SMEM_FLOATS (4 * 64 * ATT_STRIDE)
#define ATT_SMEM_BYTES  (ATT_SMEM_FLOATS * 4)

__global__ __launch_bounds__(256, 2)
void attn_kernel()
{
    extern __shared__ float sm[];
    float* Qs = sm;                        // [64][68]
    float* Ps = Qs + 64 * ATT_STRIDE;      // [64][68]
    float* Ks = Ps + 64 * ATT_STRIDE;      // [key][d]
    float* Vt = Ks + 64 * ATT_STRIDE;      // [d][key]

    const int h   = blockIdx.y;
    const int qt  = blockIdx.x;
    const int q0  = qt * 64;
    const int tid = threadIdx.x;
    const int r   = tid >> 2;
    const int cg  = tid & 3;
    const int col = h * HD;

    for (int i = tid; i < 64 * 16; i += 256) {
        int row = i >> 4;
        int c4  = (i & 15) * 4;
        float4 v = *(const float4*)&g_q[(long)(q0 + row) * DM + col + c4];
        float* dst = &Qs[row * ATT_STRIDE + c4];
        dst[0] = v.x * 0.125f;
        dst[1] = v.y * 0.125f;
        dst[2] = v.z * 0.125f;
        dst[3] = v.w * 0.125f;
    }

    float m = -1e30f, l = 0.f;
    float o[16];
#pragma unroll
    for (int j = 0; j < 16; j++) o[j] = 0.f;

    const int kt0 = (qt >= 4) ? (qt - 4) : 0;
    for (int kt = kt0; kt <= qt; kt++) {
        __syncthreads();
        for (int i = tid; i < 64 * 16; i += 256) {
            int row = i >> 4;
            int c4  = (i & 15) * 4;
            long gbase = (long)(kt * 64 + row) * DM + col + c4;
            *(float4*)&Ks[row * ATT_STRIDE + c4] = *(const float4*)&g_k[gbase];
            float4 vv = *(const float4*)&g_v[gbase];
            Vt[(c4 + 0) * ATT_STRIDE + row] = vv.x;
            Vt[(c4 + 1) * ATT_STRIDE + row] = vv.y;
            Vt[(c4 + 2) * ATT_STRIDE + row] = vv.z;
            Vt[(c4 + 3) * ATT_STRIDE + row] = vv.w;
        }
        __syncthreads();

        float s[16];
#pragma unroll
        for (int j = 0; j < 16; j++) s[j] = 0.f;
#pragma unroll 4
        for (int d4 = 0; d4 < 16; d4++) {
            float4 qv = *(float4*)&Qs[r * ATT_STRIDE + d4 * 4];
#pragma unroll
            for (int j = 0; j < 16; j++) {
                int c = cg + 4 * j;
                float4 kv = *(float4*)&Ks[c * ATT_STRIDE + d4 * 4];
                s[j] += qv.x * kv.x + qv.y * kv.y + qv.z * kv.z + qv.w * kv.w;
            }
        }

        const int iq = q0 + r;
        float tmax = -1e30f;
#pragma unroll
        for (int j = 0; j < 16; j++) {
            int jg = kt * 64 + cg + 4 * j;
            bool ok = (jg <= iq) && (iq - jg < WIN);
            s[j] = ok ? s[j] : -1e30f;
            tmax = fmaxf(tmax, s[j]);
        }
        tmax = fmaxf(tmax, __shfl_xor_sync(0xffffffffu, tmax, 1));
        tmax = fmaxf(tmax, __shfl_xor_sync(0xffffffffu, tmax, 2));

        float mnew = fmaxf(m, tmax);
        float corr = __expf(m - mnew);
        m = mnew;

        float ls = 0.f;
#pragma unroll
        for (int j = 0; j < 16; j++) {
            float p = (s[j] > -1e29f) ? __expf(s[j] - m) : 0.f;
            Ps[r * ATT_STRIDE + cg + 4 * j] = p;
            ls += p;
        }
        ls += __shfl_xor_sync(0xffffffffu, ls, 1);
        ls += __shfl_xor_sync(0xffffffffu, ls, 2);
        l = l * corr + ls;
#pragma unroll
        for (int j = 0; j < 16; j++) o[j] *= corr;

        __syncthreads();

#pragma unroll 4
        for (int k4 = 0; k4 < 16; k4++) {
            float4 pv = *(float4*)&Ps[r * ATT_STRIDE + k4 * 4];
#pragma unroll
            for (int j = 0; j < 16; j++) {
                int c = cg + 4 * j;
                float4 vv = *(float4*)&Vt[c * ATT_STRIDE + k4 * 4];
                o[j] += pv.x * vv.x + pv.y * vv.y + pv.z * vv.z + pv.w * vv.w;
            }
        }
    }

    const float inv = 1.f / l;
#pragma unroll
    for (int j = 0; j < 16; j++)
        g_att[(long)(q0 + r) * DM + col + cg + 4 * j] = o[j] * inv;
}

// ---------------------------------------------------------------------------
// Launch. Input order resolved at runtime from in_sizes (weights DM*DM,
// biases DM): grouped setup_inputs order or interleaved pair order.
// ---------------------------------------------------------------------------
extern "C" void kernel_launch(void* const* d_in, const int* in_sizes, int n_in,
                              void* d_out, int out_size)
{
    const float* x = (const float*)d_in[0];
    const float *Wq, *Wk, *Wv, *Wo, *bq, *bk, *bv, *bo;

    if (in_sizes[2] == DM) {
        Wq = (const float*)d_in[1]; bq = (const float*)d_in[2];
        Wk = (const float*)d_in[3]; bk = (const float*)d_in[4];
        Wv = (const float*)d_in[5]; bv = (const float*)d_in[6];
        Wo = (const float*)d_in[7]; bo = (const float*)d_in[8];
    } else {
        Wq = (const float*)d_in[1]; Wk = (const float*)d_in[2];
        Wv = (const float*)d_in[3]; Wo = (const float*)d_in[4];
        bq = (const float*)d_in[5]; bk = (const float*)d_in[6];
        bv = (const float*)d_in[7]; bo = (const float*)d_in[8];
    }
    float* out = (float*)d_out;

    float *q, *k, *v, *att;
    cudaGetSymbolAddress((void**)&q,   g_q);
    cudaGetSymbolAddress((void**)&k,   g_k);
    cudaGetSymbolAddress((void**)&v,   g_v);
    cudaGetSymbolAddress((void**)&att, g_att);

    cudaFuncSetAttribute(attn_kernel,
                         cudaFuncAttributeMaxDynamicSharedMemorySize,
                         ATT_SMEM_BYTES);

    dim3 gqkv(DM / GBN, SEQ / GBM, 3);
    gemm_tf32_bias<<<gqkv, 256>>>(x, Wq, Wk, Wv, bq, bk, bv, q, k, v,
                                  SEQ, DM, DM);

    dim3 gat(SEQ / 64, NH);
    attn_kernel<<<gat, 256, ATT_SMEM_BYTES>>>();

    dim3 gout(DM / GBN, SEQ / GBM, 1);
    gemm_tf32_bias<<<gout, 256>>>(att, Wo, Wo, Wo, bo, bo, bo, out, out, out,
                                  SEQ, DM, DM);
}

// round 6
// speedup vs baseline: 2.9168x; 1.6279x over previous
#include <cuda_runtime.h>
#include <cstdint>

#define SEQ   4096
#define DM    1024
#define NH    16
#define HD    64
#define WIN   256

// Scratch (allocation-free: __device__ globals)
__device__ float g_q[SEQ * DM];
__device__ float g_k[SEQ * DM];
__device__ float g_v[SEQ * DM];
__device__ float g_att[SEQ * DM];

// ---------------------------------------------------------------------------
// Common tf32 helpers
// ---------------------------------------------------------------------------
__device__ __forceinline__ uint32_t f2tf(float f) {
    uint32_t u;
    asm("cvt.rna.tf32.f32 %0, %1;" : "=r"(u) : "f"(f));
    return u;
}

__device__ __forceinline__ void mma_tf32(float (&d)[4],
                                         const uint32_t (&a)[4],
                                         const uint32_t (&b)[2]) {
    asm volatile(
        "mma.sync.aligned.m16n8k8.row.col.f32.tf32.tf32.f32 "
        "{%0,%1,%2,%3}, {%4,%5,%6,%7}, {%8,%9}, {%0,%1,%2,%3};\n"
        : "+f"(d[0]), "+f"(d[1]), "+f"(d[2]), "+f"(d[3])
        : "r"(a[0]), "r"(a[1]), "r"(a[2]), "r"(a[3]),
          "r"(b[0]), "r"(b[1]));
}

// ---------------------------------------------------------------------------
// tf32 tensor-core GEMM with bias (unchanged from Round 5 passing kernel).
// ---------------------------------------------------------------------------
#define GBM 128
#define GBN 128
#define GBK 32
#define SA  137
#define SB  136

__global__ __launch_bounds__(256, 2)
void gemm_tf32_bias(const float* __restrict__ A,
                    const float* __restrict__ B0, const float* __restrict__ B1,
                    const float* __restrict__ B2,
                    const float* __restrict__ b0, const float* __restrict__ b1,
                    const float* __restrict__ b2,
                    float* __restrict__ C0, float* __restrict__ C1,
                    float* __restrict__ C2,
                    int M, int N, int K)
{
    const float* B    = (blockIdx.z == 0) ? B0 : ((blockIdx.z == 1) ? B1 : B2);
    const float* bias = (blockIdx.z == 0) ? b0 : ((blockIdx.z == 1) ? b1 : b2);
    float*       C    = (blockIdx.z == 0) ? C0 : ((blockIdx.z == 1) ? C1 : C2);

    __shared__ uint32_t As[GBK * SA];
    __shared__ uint32_t Bs[GBK * SB];

    const int tid  = threadIdx.x;
    const int wid  = tid >> 5;
    const int lane = tid & 31;
    const int wm   = wid & 1;
    const int wn   = wid >> 1;
    const int gid  = lane >> 2;
    const int tig  = lane & 3;

    const float* Aptr = A + (long)blockIdx.y * GBM * K;
    const float* Bptr = B + blockIdx.x * GBN;

    float acc[4][4][4];
#pragma unroll
    for (int mi = 0; mi < 4; mi++)
#pragma unroll
        for (int ni = 0; ni < 4; ni++)
#pragma unroll
            for (int r = 0; r < 4; r++) acc[mi][ni][r] = 0.f;

    for (int kt = 0; kt < K; kt += GBK) {
#pragma unroll
        for (int i = 0; i < 4; i++) {
            int idx = tid + i * 256;
            int row = idx >> 3;
            int c4  = (idx & 7) * 4;
            float4 v = *(const float4*)(Aptr + (long)row * K + kt + c4);
            As[(c4 + 0) * SA + row] = f2tf(v.x);
            As[(c4 + 1) * SA + row] = f2tf(v.y);
            As[(c4 + 2) * SA + row] = f2tf(v.z);
            As[(c4 + 3) * SA + row] = f2tf(v.w);
        }
#pragma unroll
        for (int i = 0; i < 4; i++) {
            int idx = tid + i * 256;
            int row = idx >> 5;
            int c4  = (idx & 31) * 4;
            float4 v = *(const float4*)(Bptr + (long)(kt + row) * N + c4);
            uint4 w;
            w.x = f2tf(v.x); w.y = f2tf(v.y); w.z = f2tf(v.z); w.w = f2tf(v.w);
            *(uint4*)&Bs[row * SB + c4] = w;
        }
        __syncthreads();

#pragma unroll
        for (int ks = 0; ks < 4; ks++) {
            const int kb = ks * 8;
            uint32_t a[4][4], b[4][2];
#pragma unroll
            for (int mi = 0; mi < 4; mi++) {
                int m = wm * 64 + mi * 16 + gid;
                a[mi][0] = As[(kb + tig) * SA + m];
                a[mi][1] = As[(kb + tig) * SA + m + 8];
                a[mi][2] = As[(kb + tig + 4) * SA + m];
                a[mi][3] = As[(kb + tig + 4) * SA + m + 8];
            }
#pragma unroll
            for (int ni = 0; ni < 4; ni++) {
                int n = wn * 32 + ni * 8 + gid;
                b[ni][0] = Bs[(kb + tig) * SB + n];
                b[ni][1] = Bs[(kb + tig + 4) * SB + n];
            }
#pragma unroll
            for (int mi = 0; mi < 4; mi++)
#pragma unroll
                for (int ni = 0; ni < 4; ni++)
                    mma_tf32(acc[mi][ni], a[mi], b[ni]);
        }
        __syncthreads();
    }

    const int row_base = blockIdx.y * GBM + wm * 64;
    const int col_base = blockIdx.x * GBN + wn * 32;
#pragma unroll
    for (int mi = 0; mi < 4; mi++) {
#pragma unroll
        for (int ni = 0; ni < 4; ni++) {
            int r0 = row_base + mi * 16 + gid;
            int c  = col_base + ni * 8 + 2 * tig;
            float2 bv = *(const float2*)&bias[c];
            float2 o01, o23;
            o01.x = acc[mi][ni][0] + bv.x;
            o01.y = acc[mi][ni][1] + bv.y;
            o23.x = acc[mi][ni][2] + bv.x;
            o23.y = acc[mi][ni][3] + bv.y;
            *(float2*)&C[(long)r0 * N + c]       = o01;
            *(float2*)&C[(long)(r0 + 8) * N + c] = o23;
        }
    }
}

// ---------------------------------------------------------------------------
// Tensor-core sliding-window flash attention.
// CTA = (head, 128-query tile), 256 threads / 8 warps; warp w owns query rows
// [w*16, w*16+16) x all 64 keys of the current key tile.
// S = Q @ Kt (Kt = K transposed [d][key], stride 72: conflict-free b-frags and
// conflict-free scatter stores via lane-per-key mapping). P stored tf32 in
// per-warp-private Ps rows (stride 68: conflict-free a-frags). O += P @ V with
// V natural [key][d] (stride 72).
// ---------------------------------------------------------------------------
#define QT    128
#define ATS_Q 68
#define ATS_K 72
#define ATT_SMEM_BYTES ((2 * QT * ATS_Q + 2 * 64 * ATS_K) * 4)

__global__ __launch_bounds__(256, 2)
void attn_tc()
{
    extern __shared__ uint32_t smu[];
    uint32_t* Qs = smu;                       // [128][68] tf32 (scaled)
    uint32_t* Ps = Qs + QT * ATS_Q;           // [128][68] tf32
    uint32_t* Kt = Ps + QT * ATS_Q;           // [64 d][72] tf32 (K transposed)
    uint32_t* Vs = Kt + 64 * ATS_K;           // [64 key][72] tf32

    const int h    = blockIdx.y;
    const int qt   = blockIdx.x;
    const int q0   = qt * QT;
    const int tid  = threadIdx.x;
    const int wid  = tid >> 5;
    const int lane = tid & 31;
    const int gid  = lane >> 2;
    const int tig  = lane & 3;
    const int col  = h * HD;
    const int qw   = wid * 16;

    // Load + scale Q tile (coalesced), tf32.
    for (int i = tid; i < QT * 16; i += 256) {
        int row = i >> 4;
        int c4  = (i & 15) * 4;
        float4 v = *(const float4*)&g_q[(long)(q0 + row) * DM + col + c4];
        uint32_t* dst = &Qs[row * ATS_Q + c4];
        dst[0] = f2tf(v.x * 0.125f);
        dst[1] = f2tf(v.y * 0.125f);
        dst[2] = f2tf(v.z * 0.125f);
        dst[3] = f2tf(v.w * 0.125f);
    }

    const int prow0 = (qw + gid) * ATS_Q;
    const int prow1 = (qw + gid + 8) * ATS_Q;

    float m0 = -1e30f, m1 = -1e30f, l0 = 0.f, l1 = 0.f;
    float o[8][4];
#pragma unroll
    for (int ni = 0; ni < 8; ni++)
#pragma unroll
        for (int r = 0; r < 4; r++) o[ni][r] = 0.f;

    int kt_lo = 2 * qt - 4; if (kt_lo < 0) kt_lo = 0;
    const int kt_hi = 2 * qt + 1;

    for (int kt = kt_lo; kt <= kt_hi; kt++) {
        __syncthreads();   // previous iteration done reading Kt/Vs (also covers Qs after load)
        // K transposed scatter: lane-per-key mapping -> conflict-free STS.
        for (int i = tid; i < 64 * 16; i += 256) {
            int key = i & 63;
            int c4  = (i >> 6) * 4;
            float4 v = *(const float4*)&g_k[(long)(kt * 64 + key) * DM + col + c4];
            Kt[(c4 + 0) * ATS_K + key] = f2tf(v.x);
            Kt[(c4 + 1) * ATS_K + key] = f2tf(v.y);
            Kt[(c4 + 2) * ATS_K + key] = f2tf(v.z);
            Kt[(c4 + 3) * ATS_K + key] = f2tf(v.w);
        }
        // V direct (coalesced).
        for (int i = tid; i < 64 * 16; i += 256) {
            int key = i >> 4;
            int c4  = (i & 15) * 4;
            float4 v = *(const float4*)&g_v[(long)(kt * 64 + key) * DM + col + c4];
            uint4 w;
            w.x = f2tf(v.x); w.y = f2tf(v.y); w.z = f2tf(v.z); w.w = f2tf(v.w);
            *(uint4*)&Vs[key * ATS_K + c4] = w;
        }
        __syncthreads();

        // S = Q @ Kt  (8 n-tiles x 8 k-slices of m16n8k8)
        float s[8][4];
#pragma unroll
        for (int ni = 0; ni < 8; ni++)
#pragma unroll
            for (int r = 0; r < 4; r++) s[ni][r] = 0.f;

#pragma unroll
        for (int ks = 0; ks < 8; ks++) {
            const int kb = ks * 8;
            uint32_t a[4];
            a[0] = Qs[prow0 + kb + tig];
            a[1] = Qs[prow1 + kb + tig];
            a[2] = Qs[prow0 + kb + tig + 4];
            a[3] = Qs[prow1 + kb + tig + 4];
            uint32_t b[8][2];
#pragma unroll
            for (int ni = 0; ni < 8; ni++) {
                int n = ni * 8 + gid;
                b[ni][0] = Kt[(kb + tig) * ATS_K + n];
                b[ni][1] = Kt[(kb + tig + 4) * ATS_K + n];
            }
#pragma unroll
            for (int ni = 0; ni < 8; ni++) mma_tf32(s[ni], a, b[ni]);
        }

        // Mask + row stats.
        const int iq0 = q0 + qw + gid;
        const int iq1 = iq0 + 8;
        float tmax0 = -1e30f, tmax1 = -1e30f;
#pragma unroll
        for (int ni = 0; ni < 8; ni++) {
            int jg = kt * 64 + ni * 8 + 2 * tig;
            bool k0, k1;
            k0 = (jg     <= iq0) && (iq0 - jg     < WIN);
            k1 = (jg + 1 <= iq0) && (iq0 - jg - 1 < WIN);
            s[ni][0] = k0 ? s[ni][0] : -1e30f;
            s[ni][1] = k1 ? s[ni][1] : -1e30f;
            k0 = (jg     <= iq1) && (iq1 - jg     < WIN);
            k1 = (jg + 1 <= iq1) && (iq1 - jg - 1 < WIN);
            s[ni][2] = k0 ? s[ni][2] : -1e30f;
            s[ni][3] = k1 ? s[ni][3] : -1e30f;
            tmax0 = fmaxf(tmax0, fmaxf(s[ni][0], s[ni][1]));
            tmax1 = fmaxf(tmax1, fmaxf(s[ni][2], s[ni][3]));
        }
        tmax0 = fmaxf(tmax0, __shfl_xor_sync(0xffffffffu, tmax0, 1));
        tmax0 = fmaxf(tmax0, __shfl_xor_sync(0xffffffffu, tmax0, 2));
        tmax1 = fmaxf(tmax1, __shfl_xor_sync(0xffffffffu, tmax1, 1));
        tmax1 = fmaxf(tmax1, __shfl_xor_sync(0xffffffffu, tmax1, 2));

        float mn0 = fmaxf(m0, tmax0), mn1 = fmaxf(m1, tmax1);
        float corr0 = __expf(m0 - mn0), corr1 = __expf(m1 - mn1);
        m0 = mn0; m1 = mn1;

        float ls0 = 0.f, ls1 = 0.f;
#pragma unroll
        for (int ni = 0; ni < 8; ni++) {
            int c = ni * 8 + 2 * tig;
            float p0 = (s[ni][0] > -1e29f) ? __expf(s[ni][0] - m0) : 0.f;
            float p1 = (s[ni][1] > -1e29f) ? __expf(s[ni][1] - m0) : 0.f;
            float p2 = (s[ni][2] > -1e29f) ? __expf(s[ni][2] - m1) : 0.f;
            float p3 = (s[ni][3] > -1e29f) ? __expf(s[ni][3] - m1) : 0.f;
            Ps[prow0 + c]     = f2tf(p0);
            Ps[prow0 + c + 1] = f2tf(p1);
            Ps[prow1 + c]     = f2tf(p2);
            Ps[prow1 + c + 1] = f2tf(p3);
            ls0 += p0 + p1;
            ls1 += p2 + p3;
        }
        ls0 += __shfl_xor_sync(0xffffffffu, ls0, 1);
        ls0 += __shfl_xor_sync(0xffffffffu, ls0, 2);
        ls1 += __shfl_xor_sync(0xffffffffu, ls1, 1);
        ls1 += __shfl_xor_sync(0xffffffffu, ls1, 2);
        l0 = l0 * corr0 + ls0;
        l1 = l1 * corr1 + ls1;
#pragma unroll
        for (int ni = 0; ni < 8; ni++) {
            o[ni][0] *= corr0; o[ni][1] *= corr0;
            o[ni][2] *= corr1; o[ni][3] *= corr1;
        }

        __syncwarp();   // Ps rows are per-warp private: warp-level sync suffices

        // O += P @ V
#pragma unroll
        for (int ks = 0; ks < 8; ks++) {
            const int kb = ks * 8;
            uint32_t a[4];
            a[0] = Ps[prow0 + kb + tig];
            a[1] = Ps[prow1 + kb + tig];
            a[2] = Ps[prow0 + kb + tig + 4];
            a[3] = Ps[prow1 + kb + tig + 4];
            uint32_t b[8][2];
#pragma unroll
            for (int ni = 0; ni < 8; ni++) {
                int n = ni * 8 + gid;
                b[ni][0] = Vs[(kb + tig) * ATS_K + n];
                b[ni][1] = Vs[(kb + tig + 4) * ATS_K + n];
            }
#pragma unroll
            for (int ni = 0; ni < 8; ni++) mma_tf32(o[ni], a, b[ni]);
        }
    }

    // Epilogue: normalize and store.
    const float inv0 = 1.f / l0, inv1 = 1.f / l1;
    const int r0 = q0 + qw + gid;
#pragma unroll
    for (int ni = 0; ni < 8; ni++) {
        int c = col + ni * 8 + 2 * tig;
        float2 w0, w1;
        w0.x = o[ni][0] * inv0; w0.y = o[ni][1] * inv0;
        w1.x = o[ni][2] * inv1; w1.y = o[ni][3] * inv1;
        *(float2*)&g_att[(long)r0 * DM + c]       = w0;
        *(float2*)&g_att[(long)(r0 + 8) * DM + c] = w1;
    }
}

// ---------------------------------------------------------------------------
// Launch. Input order resolved at runtime from in_sizes (weights DM*DM,
// biases DM): grouped setup_inputs order or interleaved pair order.
// ---------------------------------------------------------------------------
extern "C" void kernel_launch(void* const* d_in, const int* in_sizes, int n_in,
                              void* d_out, int out_size)
{
    const float* x = (const float*)d_in[0];
    const float *Wq, *Wk, *Wv, *Wo, *bq, *bk, *bv, *bo;

    if (in_sizes[2] == DM) {
        Wq = (const float*)d_in[1]; bq = (const float*)d_in[2];
        Wk = (const float*)d_in[3]; bk = (const float*)d_in[4];
        Wv = (const float*)d_in[5]; bv = (const float*)d_in[6];
        Wo = (const float*)d_in[7]; bo = (const float*)d_in[8];
    } else {
        Wq = (const float*)d_in[1]; Wk = (const float*)d_in[2];
        Wv = (const float*)d_in[3]; Wo = (const float*)d_in[4];
        bq = (const float*)d_in[5]; bk = (const float*)d_in[6];
        bv = (const float*)d_in[7]; bo = (const float*)d_in[8];
    }
    float* out = (float*)d_out;

    float *q, *k, *v, *att;
    cudaGetSymbolAddress((void**)&q,   g_q);
    cudaGetSymbolAddress((void**)&k,   g_k);
    cudaGetSymbolAddress((void**)&v,   g_v);
    cudaGetSymbolAddress((void**)&att, g_att);

    cudaFuncSetAttribute(attn_tc,
                         cudaFuncAttributeMaxDynamicSharedMemorySize,
                         ATT_SMEM_BYTES);

    dim3 gqkv(DM / GBN, SEQ / GBM, 3);
    gemm_tf32_bias<<<gqkv, 256>>>(x, Wq, Wk, Wv, bq, bk, bv, q, k, v,
                                  SEQ, DM, DM);

    dim3 gat(SEQ / QT, NH);
    attn_tc<<<gat, 256, ATT_SMEM_BYTES>>>();

    dim3 gout(DM / GBN, SEQ / GBM, 1);
    gemm_tf32_bias<<<gout, 256>>>(att, Wo, Wo, Wo, bo, bo, bo, out, out, out,
                                  SEQ, DM, DM);
}

// round 7
// speedup vs baseline: 3.1615x; 1.0839x over previous
#include <cuda_runtime.h>
#include <cstdint>

#define SEQ   4096
#define DM    1024
#define NH    16
#define HD    64
#define WIN   256

// Scratch (allocation-free: __device__ globals)
__device__ float g_q[SEQ * DM];
__device__ float g_k[SEQ * DM];
__device__ float g_v[SEQ * DM];
__device__ float g_att[SEQ * DM];

// ---------------------------------------------------------------------------
// Common helpers
// ---------------------------------------------------------------------------
__device__ __forceinline__ uint32_t f2tf(float f) {
    uint32_t u;
    asm("cvt.rna.tf32.f32 %0, %1;" : "=r"(u) : "f"(f));
    return u;
}

__device__ __forceinline__ void mma_tf32(float (&d)[4],
                                         const uint32_t (&a)[4],
                                         const uint32_t (&b)[2]) {
    asm volatile(
        "mma.sync.aligned.m16n8k8.row.col.f32.tf32.tf32.f32 "
        "{%0,%1,%2,%3}, {%4,%5,%6,%7}, {%8,%9}, {%0,%1,%2,%3};\n"
        : "+f"(d[0]), "+f"(d[1]), "+f"(d[2]), "+f"(d[3])
        : "r"(a[0]), "r"(a[1]), "r"(a[2]), "r"(a[3]),
          "r"(b[0]), "r"(b[1]));
}

__device__ __forceinline__ void cp16(float* sdst, const float* gsrc) {
    uint32_t s = (uint32_t)__cvta_generic_to_shared(sdst);
    asm volatile("cp.async.cg.shared.global [%0], [%1], 16;\n"
                 :: "r"(s), "l"(gsrc));
}
__device__ __forceinline__ void cp_commit() {
    asm volatile("cp.async.commit_group;\n");
}
template <int N> __device__ __forceinline__ void cp_wait() {
    asm volatile("cp.async.wait_group %0;\n" :: "n"(N));
}

// ---------------------------------------------------------------------------
// tf32 tensor-core GEMM with bias, 3-stage cp.async pipeline.
// C = A[M,K] @ B[K,N] + bias; blockIdx.z selects (B, bias, C).
// CTA tile 128x128x32, 8 warps, warp tile 64x32, mma.m16n8k8.tf32.
// SMEM (raw f32, converted to tf32 after fragment load):
//   A stage [128][36] row-major  (frag banks 4*gid+tig: conflict-free)
//   B stage [32][136]            (frag banks 8*tig+gid: conflict-free)
// ---------------------------------------------------------------------------
#define GBM 128
#define GBN 128
#define GBK 32
#define SAW 36
#define SBW 136
#define ASZ (GBM * SAW)            // floats per A stage (4608)
#define BSZ (GBK * SBW)            // floats per B stage (4352)
#define GSTAGES 3
#define GEMM_SMEM_BYTES (GSTAGES * (ASZ + BSZ) * 4)   // 107520

__global__ __launch_bounds__(256, 2)
void gemm_tf32_bias(const float* __restrict__ A,
                    const float* __restrict__ B0, const float* __restrict__ B1,
                    const float* __restrict__ B2,
                    const float* __restrict__ b0, const float* __restrict__ b1,
                    const float* __restrict__ b2,
                    float* __restrict__ C0, float* __restrict__ C1,
                    float* __restrict__ C2,
                    int M, int N, int K)
{
    const float* B    = (blockIdx.z == 0) ? B0 : ((blockIdx.z == 1) ? B1 : B2);
    const float* bias = (blockIdx.z == 0) ? b0 : ((blockIdx.z == 1) ? b1 : b2);
    float*       C    = (blockIdx.z == 0) ? C0 : ((blockIdx.z == 1) ? C1 : C2);

    extern __shared__ float smg[];
    float* SAbase = smg;                    // [GSTAGES][ASZ]
    float* SBbase = smg + GSTAGES * ASZ;    // [GSTAGES][BSZ]

    const int tid  = threadIdx.x;
    const int wid  = tid >> 5;
    const int lane = tid & 31;
    const int wm   = wid & 1;
    const int wn   = wid >> 1;
    const int gid  = lane >> 2;
    const int tig  = lane & 3;

    const float* Aptr = A + (long)blockIdx.y * GBM * K;
    const float* Bptr = B + blockIdx.x * GBN;

    // Staging decomposition (per thread: 4 x 16B for A, 4 x 16B for B)
    const int arow = tid >> 3;            // 0..31, +32 per iter
    const int ac   = (tid & 7) * 4;       // 0..28
    const int brow = tid >> 5;            // 0..7, +8 per iter
    const int bc   = (tid & 31) * 4;      // 0..124

    float acc[4][4][4];
#pragma unroll
    for (int mi = 0; mi < 4; mi++)
#pragma unroll
        for (int ni = 0; ni < 4; ni++)
#pragma unroll
            for (int r = 0; r < 4; r++) acc[mi][ni][r] = 0.f;

    const int NT = K / GBK;   // 32

#define GEMM_ISSUE(KT, S)                                                     \
    do {                                                                      \
        float* as_ = SAbase + (S) * ASZ;                                      \
        float* bs_ = SBbase + (S) * BSZ;                                      \
        _Pragma("unroll")                                                     \
        for (int i_ = 0; i_ < 4; i_++) {                                      \
            int r_ = arow + i_ * 32;                                          \
            cp16(as_ + r_ * SAW + ac,                                         \
                 Aptr + (long)r_ * K + (KT) * GBK + ac);                      \
        }                                                                     \
        _Pragma("unroll")                                                     \
        for (int i_ = 0; i_ < 4; i_++) {                                      \
            int r_ = brow + i_ * 8;                                           \
            cp16(bs_ + r_ * SBW + bc,                                         \
                 Bptr + (long)((KT) * GBK + r_) * N + bc);                    \
        }                                                                     \
    } while (0)

    GEMM_ISSUE(0, 0); cp_commit();
    GEMM_ISSUE(1, 1); cp_commit();

    for (int kt = 0; kt < NT; kt++) {
        const int s = kt % GSTAGES;
        if (kt + 2 < NT) cp_wait<1>(); else cp_wait<0>();
        __syncthreads();   // stage s ready; also write-after-read guard
        if (kt + 2 < NT) { GEMM_ISSUE(kt + 2, (kt + 2) % GSTAGES); cp_commit(); }

        const float* as = SAbase + s * ASZ;
        const float* bs = SBbase + s * BSZ;

#pragma unroll
        for (int ks = 0; ks < 4; ks++) {
            const int kb = ks * 8;
            uint32_t a[4][4], b[4][2];
#pragma unroll
            for (int mi = 0; mi < 4; mi++) {
                int m = wm * 64 + mi * 16 + gid;
                a[mi][0] = f2tf(as[(m)     * SAW + kb + tig]);
                a[mi][1] = f2tf(as[(m + 8) * SAW + kb + tig]);
                a[mi][2] = f2tf(as[(m)     * SAW + kb + tig + 4]);
                a[mi][3] = f2tf(as[(m + 8) * SAW + kb + tig + 4]);
            }
#pragma unroll
            for (int ni = 0; ni < 4; ni++) {
                int n = wn * 32 + ni * 8 + gid;
                b[ni][0] = f2tf(bs[(kb + tig)     * SBW + n]);
                b[ni][1] = f2tf(bs[(kb + tig + 4) * SBW + n]);
            }
#pragma unroll
            for (int mi = 0; mi < 4; mi++)
#pragma unroll
                for (int ni = 0; ni < 4; ni++)
                    mma_tf32(acc[mi][ni], a[mi], b[ni]);
        }
    }
#undef GEMM_ISSUE

    const int row_base = blockIdx.y * GBM + wm * 64;
    const int col_base = blockIdx.x * GBN + wn * 32;
#pragma unroll
    for (int mi = 0; mi < 4; mi++) {
#pragma unroll
        for (int ni = 0; ni < 4; ni++) {
            int r0 = row_base + mi * 16 + gid;
            int c  = col_base + ni * 8 + 2 * tig;
            float2 bv = *(const float2*)&bias[c];
            float2 o01, o23;
            o01.x = acc[mi][ni][0] + bv.x;
            o01.y = acc[mi][ni][1] + bv.y;
            o23.x = acc[mi][ni][2] + bv.x;
            o23.y = acc[mi][ni][3] + bv.y;
            *(float2*)&C[(long)r0 * N + c]       = o01;
            *(float2*)&C[(long)(r0 + 8) * N + c] = o23;
        }
    }
}

// ---------------------------------------------------------------------------
// Tensor-core sliding-window flash attention (unchanged from Round 6 pass).
// ---------------------------------------------------------------------------
#define QT    128
#define ATS_Q 68
#define ATS_K 72
#define ATT_SMEM_BYTES ((2 * QT * ATS_Q + 2 * 64 * ATS_K) * 4)

__global__ __launch_bounds__(256, 2)
void attn_tc()
{
    extern __shared__ uint32_t smu[];
    uint32_t* Qs = smu;                       // [128][68] tf32 (scaled)
    uint32_t* Ps = Qs + QT * ATS_Q;           // [128][68] tf32
    uint32_t* Kt = Ps + QT * ATS_Q;           // [64 d][72] tf32 (K transposed)
    uint32_t* Vs = Kt + 64 * ATS_K;           // [64 key][72] tf32

    const int h    = blockIdx.y;
    const int qt   = blockIdx.x;
    const int q0   = qt * QT;
    const int tid  = threadIdx.x;
    const int wid  = tid >> 5;
    const int lane = tid & 31;
    const int gid  = lane >> 2;
    const int tig  = lane & 3;
    const int col  = h * HD;
    const int qw   = wid * 16;

    for (int i = tid; i < QT * 16; i += 256) {
        int row = i >> 4;
        int c4  = (i & 15) * 4;
        float4 v = *(const float4*)&g_q[(long)(q0 + row) * DM + col + c4];
        uint32_t* dst = &Qs[row * ATS_Q + c4];
        dst[0] = f2tf(v.x * 0.125f);
        dst[1] = f2tf(v.y * 0.125f);
        dst[2] = f2tf(v.z * 0.125f);
        dst[3] = f2tf(v.w * 0.125f);
    }

    const int prow0 = (qw + gid) * ATS_Q;
    const int prow1 = (qw + gid + 8) * ATS_Q;

    float m0 = -1e30f, m1 = -1e30f, l0 = 0.f, l1 = 0.f;
    float o[8][4];
#pragma unroll
    for (int ni = 0; ni < 8; ni++)
#pragma unroll
        for (int r = 0; r < 4; r++) o[ni][r] = 0.f;

    int kt_lo = 2 * qt - 4; if (kt_lo < 0) kt_lo = 0;
    const int kt_hi = 2 * qt + 1;

    for (int kt = kt_lo; kt <= kt_hi; kt++) {
        __syncthreads();
        for (int i = tid; i < 64 * 16; i += 256) {
            int key = i & 63;
            int c4  = (i >> 6) * 4;
            float4 v = *(const float4*)&g_k[(long)(kt * 64 + key) * DM + col + c4];
            Kt[(c4 + 0) * ATS_K + key] = f2tf(v.x);
            Kt[(c4 + 1) * ATS_K + key] = f2tf(v.y);
            Kt[(c4 + 2) * ATS_K + key] = f2tf(v.z);
            Kt[(c4 + 3) * ATS_K + key] = f2tf(v.w);
        }
        for (int i = tid; i < 64 * 16; i += 256) {
            int key = i >> 4;
            int c4  = (i & 15) * 4;
            float4 v = *(const float4*)&g_v[(long)(kt * 64 + key) * DM + col + c4];
            uint4 w;
            w.x = f2tf(v.x); w.y = f2tf(v.y); w.z = f2tf(v.z); w.w = f2tf(v.w);
            *(uint4*)&Vs[key * ATS_K + c4] = w;
        }
        __syncthreads();

        float s[8][4];
#pragma unroll
        for (int ni = 0; ni < 8; ni++)
#pragma unroll
            for (int r = 0; r < 4; r++) s[ni][r] = 0.f;

#pragma unroll
        for (int ks = 0; ks < 8; ks++) {
            const int kb = ks * 8;
            uint32_t a[4];
            a[0] = Qs[prow0 + kb + tig];
            a[1] = Qs[prow1 + kb + tig];
            a[2] = Qs[prow0 + kb + tig + 4];
            a[3] = Qs[prow1 + kb + tig + 4];
            uint32_t b[8][2];
#pragma unroll
            for (int ni = 0; ni < 8; ni++) {
                int n = ni * 8 + gid;
                b[ni][0] = Kt[(kb + tig) * ATS_K + n];
                b[ni][1] = Kt[(kb + tig + 4) * ATS_K + n];
            }
#pragma unroll
            for (int ni = 0; ni < 8; ni++) mma_tf32(s[ni], a, b[ni]);
        }

        const int iq0 = q0 + qw + gid;
        const int iq1 = iq0 + 8;
        float tmax0 = -1e30f, tmax1 = -1e30f;
#pragma unroll
        for (int ni = 0; ni < 8; ni++) {
            int jg = kt * 64 + ni * 8 + 2 * tig;
            bool k0, k1;
            k0 = (jg     <= iq0) && (iq0 - jg     < WIN);
            k1 = (jg + 1 <= iq0) && (iq0 - jg - 1 < WIN);
            s[ni][0] = k0 ? s[ni][0] : -1e30f;
            s[ni][1] = k1 ? s[ni][1] : -1e30f;
            k0 = (jg     <= iq1) && (iq1 - jg     < WIN);
            k1 = (jg + 1 <= iq1) && (iq1 - jg - 1 < WIN);
            s[ni][2] = k0 ? s[ni][2] : -1e30f;
            s[ni][3] = k1 ? s[ni][3] : -1e30f;
            tmax0 = fmaxf(tmax0, fmaxf(s[ni][0], s[ni][1]));
            tmax1 = fmaxf(tmax1, fmaxf(s[ni][2], s[ni][3]));
        }
        tmax0 = fmaxf(tmax0, __shfl_xor_sync(0xffffffffu, tmax0, 1));
        tmax0 = fmaxf(tmax0, __shfl_xor_sync(0xffffffffu, tmax0, 2));
        tmax1 = fmaxf(tmax1, __shfl_xor_sync(0xffffffffu, tmax1, 1));
        tmax1 = fmaxf(tmax1, __shfl_xor_sync(0xffffffffu, tmax1, 2));

        float mn0 = fmaxf(m0, tmax0), mn1 = fmaxf(m1, tmax1);
        float corr0 = __expf(m0 - mn0), corr1 = __expf(m1 - mn1);
        m0 = mn0; m1 = mn1;

        float ls0 = 0.f, ls1 = 0.f;
#pragma unroll
        for (int ni = 0; ni < 8; ni++) {
            int c = ni * 8 + 2 * tig;
            float p0 = (s[ni][0] > -1e29f) ? __expf(s[ni][0] - m0) : 0.f;
            float p1 = (s[ni][1] > -1e29f) ? __expf(s[ni][1] - m0) : 0.f;
            float p2 = (s[ni][2] > -1e29f) ? __expf(s[ni][2] - m1) : 0.f;
            float p3 = (s[ni][3] > -1e29f) ? __expf(s[ni][3] - m1) : 0.f;
            Ps[prow0 + c]     = f2tf(p0);
            Ps[prow0 + c + 1] = f2tf(p1);
            Ps[prow1 + c]     = f2tf(p2);
            Ps[prow1 + c + 1] = f2tf(p3);
            ls0 += p0 + p1;
            ls1 += p2 + p3;
        }
        ls0 += __shfl_xor_sync(0xffffffffu, ls0, 1);
        ls0 += __shfl_xor_sync(0xffffffffu, ls0, 2);
        ls1 += __shfl_xor_sync(0xffffffffu, ls1, 1);
        ls1 += __shfl_xor_sync(0xffffffffu, ls1, 2);
        l0 = l0 * corr0 + ls0;
        l1 = l1 * corr1 + ls1;
#pragma unroll
        for (int ni = 0; ni < 8; ni++) {
            o[ni][0] *= corr0; o[ni][1] *= corr0;
            o[ni][2] *= corr1; o[ni][3] *= corr1;
        }

        __syncwarp();

#pragma unroll
        for (int ks = 0; ks < 8; ks++) {
            const int kb = ks * 8;
            uint32_t a[4];
            a[0] = Ps[prow0 + kb + tig];
            a[1] = Ps[prow1 + kb + tig];
            a[2] = Ps[prow0 + kb + tig + 4];
            a[3] = Ps[prow1 + kb + tig + 4];
            uint32_t b[8][2];
#pragma unroll
            for (int ni = 0; ni < 8; ni++) {
                int n = ni * 8 + gid;
                b[ni][0] = Vs[(kb + tig) * ATS_K + n];
                b[ni][1] = Vs[(kb + tig + 4) * ATS_K + n];
            }
#pragma unroll
            for (int ni = 0; ni < 8; ni++) mma_tf32(o[ni], a, b[ni]);
        }
    }

    const float inv0 = 1.f / l0, inv1 = 1.f / l1;
    const int r0 = q0 + qw + gid;
#pragma unroll
    for (int ni = 0; ni < 8; ni++) {
        int c = col + ni * 8 + 2 * tig;
        float2 w0, w1;
        w0.x = o[ni][0] * inv0; w0.y = o[ni][1] * inv0;
        w1.x = o[ni][2] * inv1; w1.y = o[ni][3] * inv1;
        *(float2*)&g_att[(long)r0 * DM + c]       = w0;
        *(float2*)&g_att[(long)(r0 + 8) * DM + c] = w1;
    }
}

// ---------------------------------------------------------------------------
// Launch. Input order resolved at runtime from in_sizes (weights DM*DM,
// biases DM): grouped setup_inputs order or interleaved pair order.
// ---------------------------------------------------------------------------
extern "C" void kernel_launch(void* const* d_in, const int* in_sizes, int n_in,
                              void* d_out, int out_size)
{
    const float* x = (const float*)d_in[0];
    const float *Wq, *Wk, *Wv, *Wo, *bq, *bk, *bv, *bo;

    if (in_sizes[2] == DM) {
        Wq = (const float*)d_in[1]; bq = (const float*)d_in[2];
        Wk = (const float*)d_in[3]; bk = (const float*)d_in[4];
        Wv = (const float*)d_in[5]; bv = (const float*)d_in[6];
        Wo = (const float*)d_in[7]; bo = (const float*)d_in[8];
    } else {
        Wq = (const float*)d_in[1]; Wk = (const float*)d_in[2];
        Wv = (const float*)d_in[3]; Wo = (const float*)d_in[4];
        bq = (const float*)d_in[5]; bk = (const float*)d_in[6];
        bv = (const float*)d_in[7]; bo = (const float*)d_in[8];
    }
    float* out = (float*)d_out;

    float *q, *k, *v, *att;
    cudaGetSymbolAddress((void**)&q,   g_q);
    cudaGetSymbolAddress((void**)&k,   g_k);
    cudaGetSymbolAddress((void**)&v,   g_v);
    cudaGetSymbolAddress((void**)&att, g_att);

    cudaFuncSetAttribute(gemm_tf32_bias,
                         cudaFuncAttributeMaxDynamicSharedMemorySize,
                         GEMM_SMEM_BYTES);
    cudaFuncSetAttribute(attn_tc,
                         cudaFuncAttributeMaxDynamicSharedMemorySize,
                         ATT_SMEM_BYTES);

    dim3 gqkv(DM / GBN, SEQ / GBM, 3);
    gemm_tf32_bias<<<gqkv, 256, GEMM_SMEM_BYTES>>>(x, Wq, Wk, Wv, bq, bk, bv,
                                                   q, k, v, SEQ, DM, DM);

    dim3 gat(SEQ / QT, NH);
    attn_tc<<<gat, 256, ATT_SMEM_BYTES>>>();

    dim3 gout(DM / GBN, SEQ / GBM, 1);
    gemm_tf32_bias<<<gout, 256, GEMM_SMEM_BYTES>>>(att, Wo, Wo, Wo, bo, bo, bo,
                                                   out, out, out, SEQ, DM, DM);
}

// round 9
// speedup vs baseline: 3.3091x; 1.0467x over previous
#include <cuda_runtime.h>
#include <cstdint>

#define SEQ   4096
#define DM    1024
#define NH    16
#define HD    64
#define WIN   256

// Scratch (allocation-free: __device__ globals)
__device__ float g_q[SEQ * DM];
__device__ float g_k[SEQ * DM];
__device__ float g_v[SEQ * DM];
__device__ float g_att[SEQ * DM];
__device__ float g_xtf[SEQ * DM];        // x pre-rounded to tf32
__device__ float g_wtf[4 * DM * DM];     // Wq,Wk,Wv,Wo pre-rounded to tf32

// ---------------------------------------------------------------------------
// Common helpers
// ---------------------------------------------------------------------------
__device__ __forceinline__ uint32_t f2tf(float f) {
    uint32_t u;
    asm("cvt.rna.tf32.f32 %0, %1;" : "=r"(u) : "f"(f));
    return u;
}

__device__ __forceinline__ void mma_tf32(float (&d)[4],
                                         const uint32_t (&a)[4],
                                         const uint32_t (&b)[2]) {
    asm volatile(
        "mma.sync.aligned.m16n8k8.row.col.f32.tf32.tf32.f32 "
        "{%0,%1,%2,%3}, {%4,%5,%6,%7}, {%8,%9}, {%0,%1,%2,%3};\n"
        : "+f"(d[0]), "+f"(d[1]), "+f"(d[2]), "+f"(d[3])
        : "r"(a[0]), "r"(a[1]), "r"(a[2]), "r"(a[3]),
          "r"(b[0]), "r"(b[1]));
}

__device__ __forceinline__ void cp16(float* sdst, const float* gsrc) {
    uint32_t s = (uint32_t)__cvta_generic_to_shared(sdst);
    asm volatile("cp.async.cg.shared.global [%0], [%1], 16;\n"
                 :: "r"(s), "l"(gsrc));
}
__device__ __forceinline__ void cp_commit() {
    asm volatile("cp.async.commit_group;\n");
}
template <int N> __device__ __forceinline__ void cp_wait() {
    asm volatile("cp.async.wait_group %0;\n" :: "n"(N));
}

// ---------------------------------------------------------------------------
// tf32 pre-rounding kernels (cvt.rna once in GMEM, removed from mainloops).
// ---------------------------------------------------------------------------
__global__ __launch_bounds__(256)
void round_x_kernel(const float* __restrict__ src, float* __restrict__ dst)
{
    int i = blockIdx.x * 256 + threadIdx.x;   // n4 = SEQ*DM/4
    float4 v = ((const float4*)src)[i];
    uint4 w;
    w.x = f2tf(v.x); w.y = f2tf(v.y); w.z = f2tf(v.z); w.w = f2tf(v.w);
    ((uint4*)dst)[i] = w;
}

__global__ __launch_bounds__(256)
void round_w_kernel(const float* __restrict__ W0, const float* __restrict__ W1,
                    const float* __restrict__ W2, const float* __restrict__ W3,
                    float* __restrict__ dst)
{
    const float* W = (blockIdx.z == 0) ? W0 : (blockIdx.z == 1) ? W1
                   : (blockIdx.z == 2) ? W2 : W3;
    int i = blockIdx.x * 256 + threadIdx.x;   // n4 = DM*DM/4
    float4 v = ((const float4*)W)[i];
    uint4 w;
    w.x = f2tf(v.x); w.y = f2tf(v.y); w.z = f2tf(v.z); w.w = f2tf(v.w);
    ((uint4*)(dst + (size_t)blockIdx.z * DM * DM))[i] = w;
}

// ---------------------------------------------------------------------------
// tf32 tensor-core GEMM with bias, 3-stage cp.async pipeline.
// Inputs are PRE-ROUNDED tf32 bits; mainloop is pure LDS -> MMA with
// double-buffered fragments. ROUND_C: round output to tf32 (for q/k/v, whose
// only consumer is the tf32 attention).
// ---------------------------------------------------------------------------
#define GBM 128
#define GBN 128
#define GBK 32
#define SAW 36
#define SBW 136
#define ASZ (GBM * SAW)
#define BSZ (GBK * SBW)
#define GSTAGES 3
#define GEMM_SMEM_BYTES (GSTAGES * (ASZ + BSZ) * 4)   // 107520

template <bool ROUND_C>
__global__ __launch_bounds__(256, 2)
void gemm_tf32_bias(const float* __restrict__ A,
                    const float* __restrict__ B0, const float* __restrict__ B1,
                    const float* __restrict__ B2,
                    const float* __restrict__ b0, const float* __restrict__ b1,
                    const float* __restrict__ b2,
                    float* __restrict__ C0, float* __restrict__ C1,
                    float* __restrict__ C2,
                    int M, int N, int K)
{
    const float* B    = (blockIdx.z == 0) ? B0 : ((blockIdx.z == 1) ? B1 : B2);
    const float* bias = (blockIdx.z == 0) ? b0 : ((blockIdx.z == 1) ? b1 : b2);
    float*       C    = (blockIdx.z == 0) ? C0 : ((blockIdx.z == 1) ? C1 : C2);

    extern __shared__ float smg[];
    float* SAbase = smg;
    float* SBbase = smg + GSTAGES * ASZ;

    const int tid  = threadIdx.x;
    const int wid  = tid >> 5;
    const int lane = tid & 31;
    const int wm   = wid & 1;
    const int wn   = wid >> 1;
    const int gid  = lane >> 2;
    const int tig  = lane & 3;

    const float* Aptr = A + (long)blockIdx.y * GBM * K;
    const float* Bptr = B + blockIdx.x * GBN;

    const int arow = tid >> 3;
    const int ac   = (tid & 7) * 4;
    const int brow = tid >> 5;
    const int bc   = (tid & 31) * 4;

    float acc[4][4][4];
#pragma unroll
    for (int mi = 0; mi < 4; mi++)
#pragma unroll
        for (int ni = 0; ni < 4; ni++)
#pragma unroll
            for (int r = 0; r < 4; r++) acc[mi][ni][r] = 0.f;

    const int NT = K / GBK;

#define GEMM_ISSUE(KT, S)                                                     \
    do {                                                                      \
        float* as_ = SAbase + (S) * ASZ;                                      \
        float* bs_ = SBbase + (S) * BSZ;                                      \
        _Pragma("unroll")                                                     \
        for (int i_ = 0; i_ < 4; i_++) {                                      \
            int r_ = arow + i_ * 32;                                          \
            cp16(as_ + r_ * SAW + ac,                                         \
                 Aptr + (long)r_ * K + (KT) * GBK + ac);                      \
        }                                                                     \
        _Pragma("unroll")                                                     \
        for (int i_ = 0; i_ < 4; i_++) {                                      \
            int r_ = brow + i_ * 8;                                           \
            cp16(bs_ + r_ * SBW + bc,                                         \
                 Bptr + (long)((KT) * GBK + r_) * N + bc);                    \
        }                                                                     \
    } while (0)

#define LOAD_FRAGS(BUF, KB)                                                   \
    do {                                                                      \
        _Pragma("unroll")                                                     \
        for (int mi = 0; mi < 4; mi++) {                                      \
            int m = wm * 64 + mi * 16 + gid;                                  \
            af[BUF][mi][0] = asu[(m)     * SAW + (KB) + tig];                 \
            af[BUF][mi][1] = asu[(m + 8) * SAW + (KB) + tig];                 \
            af[BUF][mi][2] = asu[(m)     * SAW + (KB) + tig + 4];             \
            af[BUF][mi][3] = asu[(m + 8) * SAW + (KB) + tig + 4];             \
        }                                                                     \
        _Pragma("unroll")                                                     \
        for (int ni = 0; ni < 4; ni++) {                                      \
            int n = wn * 32 + ni * 8 + gid;                                   \
            bf[BUF][ni][0] = bsu[((KB) + tig)     * SBW + n];                 \
            bf[BUF][ni][1] = bsu[((KB) + tig + 4) * SBW + n];                 \
        }                                                                     \
    } while (0)

    GEMM_ISSUE(0, 0); cp_commit();
    GEMM_ISSUE(1, 1); cp_commit();

    for (int kt = 0; kt < NT; kt++) {
        const int s = kt % GSTAGES;
        if (kt + 2 < NT) cp_wait<1>(); else cp_wait<0>();
        __syncthreads();
        if (kt + 2 < NT) { GEMM_ISSUE(kt + 2, (kt + 2) % GSTAGES); cp_commit(); }

        const uint32_t* asu = (const uint32_t*)(SAbase + s * ASZ);
        const uint32_t* bsu = (const uint32_t*)(SBbase + s * BSZ);

        uint32_t af[2][4][4], bf[2][4][2];
        LOAD_FRAGS(0, 0);
#pragma unroll
        for (int ks = 0; ks < 4; ks++) {
            const int cur = ks & 1;
            if (ks < 3) {
                const int nxt = cur ^ 1;
                LOAD_FRAGS(nxt, (ks + 1) * 8);
            }
#pragma unroll
            for (int mi = 0; mi < 4; mi++)
#pragma unroll
                for (int ni = 0; ni < 4; ni++)
                    mma_tf32(acc[mi][ni], af[cur][mi], bf[cur][ni]);
        }
    }
#undef GEMM_ISSUE
#undef LOAD_FRAGS

    const int row_base = blockIdx.y * GBM + wm * 64;
    const int col_base = blockIdx.x * GBN + wn * 32;
#pragma unroll
    for (int mi = 0; mi < 4; mi++) {
#pragma unroll
        for (int ni = 0; ni < 4; ni++) {
            int r0 = row_base + mi * 16 + gid;
            int c  = col_base + ni * 8 + 2 * tig;
            float2 bv = *(const float2*)&bias[c];
            float2 o01, o23;
            o01.x = acc[mi][ni][0] + bv.x;
            o01.y = acc[mi][ni][1] + bv.y;
            o23.x = acc[mi][ni][2] + bv.x;
            o23.y = acc[mi][ni][3] + bv.y;
            if (ROUND_C) {
                o01.x = __uint_as_float(f2tf(o01.x));
                o01.y = __uint_as_float(f2tf(o01.y));
                o23.x = __uint_as_float(f2tf(o23.x));
                o23.y = __uint_as_float(f2tf(o23.y));
            }
            *(float2*)&C[(long)r0 * N + c]       = o01;
            *(float2*)&C[(long)(r0 + 8) * N + c] = o23;
        }
    }
}

// ---------------------------------------------------------------------------
// Tensor-core sliding-window flash attention. q/k/v arrive PRE-ROUNDED tf32,
// so staging is pure bit-copy (Q additionally scaled by exact 2^-3).
// ---------------------------------------------------------------------------
#define QT    128
#define ATS_Q 68
#define ATS_K 72
#define ATT_SMEM_BYTES ((2 * QT * ATS_Q + 2 * 64 * ATS_K) * 4)

__global__ __launch_bounds__(256, 2)
void attn_tc()
{
    extern __shared__ uint32_t smu[];
    uint32_t* Qs = smu;                       // [128][68] tf32 (scaled)
    uint32_t* Ps = Qs + QT * ATS_Q;           // [128][68] tf32
    uint32_t* Kt = Ps + QT * ATS_Q;           // [64 d][72] tf32 (K transposed)
    uint32_t* Vs = Kt + 64 * ATS_K;           // [64 key][72] tf32

    const int h    = blockIdx.y;
    const int qt   = blockIdx.x;
    const int q0   = qt * QT;
    const int tid  = threadIdx.x;
    const int wid  = tid >> 5;
    const int lane = tid & 31;
    const int gid  = lane >> 2;
    const int tig  = lane & 3;
    const int col  = h * HD;
    const int qw   = wid * 16;

    for (int i = tid; i < QT * 16; i += 256) {
        int row = i >> 4;
        int c4  = (i & 15) * 4;
        float4 v = *(const float4*)&g_q[(long)(q0 + row) * DM + col + c4];
        uint32_t* dst = &Qs[row * ATS_Q + c4];
        dst[0] = __float_as_uint(v.x * 0.125f);   // exact: q already tf32
        dst[1] = __float_as_uint(v.y * 0.125f);
        dst[2] = __float_as_uint(v.z * 0.125f);
        dst[3] = __float_as_uint(v.w * 0.125f);
    }

    const int prow0 = (qw + gid) * ATS_Q;
    const int prow1 = (qw + gid + 8) * ATS_Q;

    float m0 = -1e30f, m1 = -1e30f, l0 = 0.f, l1 = 0.f;
    float o[8][4];
#pragma unroll
    for (int ni = 0; ni < 8; ni++)
#pragma unroll
        for (int r = 0; r < 4; r++) o[ni][r] = 0.f;

    int kt_lo = 2 * qt - 4; if (kt_lo < 0) kt_lo = 0;
    const int kt_hi = 2 * qt + 1;

    for (int kt = kt_lo; kt <= kt_hi; kt++) {
        __syncthreads();
        for (int i = tid; i < 64 * 16; i += 256) {
            int key = i & 63;
            int c4  = (i >> 6) * 4;
            uint4 v = *(const uint4*)&g_k[(long)(kt * 64 + key) * DM + col + c4];
            Kt[(c4 + 0) * ATS_K + key] = v.x;
            Kt[(c4 + 1) * ATS_K + key] = v.y;
            Kt[(c4 + 2) * ATS_K + key] = v.z;
            Kt[(c4 + 3) * ATS_K + key] = v.w;
        }
        for (int i = tid; i < 64 * 16; i += 256) {
            int key = i >> 4;
            int c4  = (i & 15) * 4;
            *(uint4*)&Vs[key * ATS_K + c4] =
                *(const uint4*)&g_v[(long)(kt * 64 + key) * DM + col + c4];
        }
        __syncthreads();

        float s[8][4];
#pragma unroll
        for (int ni = 0; ni < 8; ni++)
#pragma unroll
            for (int r = 0; r < 4; r++) s[ni][r] = 0.f;

#pragma unroll
        for (int ks = 0; ks < 8; ks++) {
            const int kb = ks * 8;
            uint32_t a[4];
            a[0] = Qs[prow0 + kb + tig];
            a[1] = Qs[prow1 + kb + tig];
            a[2] = Qs[prow0 + kb + tig + 4];
            a[3] = Qs[prow1 + kb + tig + 4];
            uint32_t b[8][2];
#pragma unroll
            for (int ni = 0; ni < 8; ni++) {
                int n = ni * 8 + gid;
                b[ni][0] = Kt[(kb + tig) * ATS_K + n];
                b[ni][1] = Kt[(kb + tig + 4) * ATS_K + n];
            }
#pragma unroll
            for (int ni = 0; ni < 8; ni++) mma_tf32(s[ni], a, b[ni]);
        }

        const int iq0 = q0 + qw + gid;
        const int iq1 = iq0 + 8;
        float tmax0 = -1e30f, tmax1 = -1e30f;
#pragma unroll
        for (int ni = 0; ni < 8; ni++) {
            int jg = kt * 64 + ni * 8 + 2 * tig;
            bool k0, k1;
            k0 = (jg     <= iq0) && (iq0 - jg     < WIN);
            k1 = (jg + 1 <= iq0) && (iq0 - jg - 1 < WIN);
            s[ni][0] = k0 ? s[ni][0] : -1e30f;
            s[ni][1] = k1 ? s[ni][1] : -1e30f;
            k0 = (jg     <= iq1) && (iq1 - jg     < WIN);
            k1 = (jg + 1 <= iq1) && (iq1 - jg - 1 < WIN);
            s[ni][2] = k0 ? s[ni][2] : -1e30f;
            s[ni][3] = k1 ? s[ni][3] : -1e30f;
            tmax0 = fmaxf(tmax0, fmaxf(s[ni][0], s[ni][1]));
            tmax1 = fmaxf(tmax1, fmaxf(s[ni][2], s[ni][3]));
        }
        tmax0 = fmaxf(tmax0, __shfl_xor_sync(0xffffffffu, tmax0, 1));
        tmax0 = fmaxf(tmax0, __shfl_xor_sync(0xffffffffu, tmax0, 2));
        tmax1 = fmaxf(tmax1, __shfl_xor_sync(0xffffffffu, tmax1, 1));
        tmax1 = fmaxf(tmax1, __shfl_xor_sync(0xffffffffu, tmax1, 2));

        float mn0 = fmaxf(m0, tmax0), mn1 = fmaxf(m1, tmax1);
        float corr0 = __expf(m0 - mn0), corr1 = __expf(m1 - mn1);
        m0 = mn0; m1 = mn1;

        float ls0 = 0.f, ls1 = 0.f;
#pragma unroll
        for (int ni = 0; ni < 8; ni++) {
            int c = ni * 8 + 2 * tig;
            float p0 = (s[ni][0] > -1e29f) ? __expf(s[ni][0] - m0) : 0.f;
            float p1 = (s[ni][1] > -1e29f) ? __expf(s[ni][1] - m0) : 0.f;
            float p2 = (s[ni][2] > -1e29f) ? __expf(s[ni][2] - m1) : 0.f;
            float p3 = (s[ni][3] > -1e29f) ? __expf(s[ni][3] - m1) : 0.f;
            Ps[prow0 + c]     = f2tf(p0);
            Ps[prow0 + c + 1] = f2tf(p1);
            Ps[prow1 + c]     = f2tf(p2);
            Ps[prow1 + c + 1] = f2tf(p3);
            ls0 += p0 + p1;
            ls1 += p2 + p3;
        }
        ls0 += __shfl_xor_sync(0xffffffffu, ls0, 1);
        ls0 += __shfl_xor_sync(0xffffffffu, ls0, 2);
        ls1 += __shfl_xor_sync(0xffffffffu, ls1, 1);
        ls1 += __shfl_xor_sync(0xffffffffu, ls1, 2);
        l0 = l0 * corr0 + ls0;
        l1 = l1 * corr1 + ls1;
#pragma unroll
        for (int ni = 0; ni < 8; ni++) {
            o[ni][0] *= corr0; o[ni][1] *= corr0;
            o[ni][2] *= corr1; o[ni][3] *= corr1;
        }

        __syncwarp();

#pragma unroll
        for (int ks = 0; ks < 8; ks++) {
            const int kb = ks * 8;
            uint32_t a[4];
            a[0] = Ps[prow0 + kb + tig];
            a[1] = Ps[prow1 + kb + tig];
            a[2] = Ps[prow0 + kb + tig + 4];
            a[3] = Ps[prow1 + kb + tig + 4];
            uint32_t b[8][2];
#pragma unroll
            for (int ni = 0; ni < 8; ni++) {
                int n = ni * 8 + gid;
                b[ni][0] = Vs[(kb + tig) * ATS_K + n];
                b[ni][1] = Vs[(kb + tig + 4) * ATS_K + n];
            }
#pragma unroll
            for (int ni = 0; ni < 8; ni++) mma_tf32(o[ni], a, b[ni]);
        }
    }

    // Epilogue: normalize, round to tf32 (consumer is the tf32 Wo GEMM).
    const float inv0 = 1.f / l0, inv1 = 1.f / l1;
    const int r0 = q0 + qw + gid;
#pragma unroll
    for (int ni = 0; ni < 8; ni++) {
        int c = col + ni * 8 + 2 * tig;
        float2 w0, w1;
        w0.x = __uint_as_float(f2tf(o[ni][0] * inv0));
        w0.y = __uint_as_float(f2tf(o[ni][1] * inv0));
        w1.x = __uint_as_float(f2tf(o[ni][2] * inv1));
        w1.y = __uint_as_float(f2tf(o[ni][3] * inv1));
        *(float2*)&g_att[(long)r0 * DM + c]       = w0;
        *(float2*)&g_att[(long)(r0 + 8) * DM + c] = w1;
    }
}

// ---------------------------------------------------------------------------
// Launch. Input order resolved at runtime from in_sizes (weights DM*DM,
// biases DM): grouped setup_inputs order or interleaved pair order.
// ---------------------------------------------------------------------------
extern "C" void kernel_launch(void* const* d_in, const int* in_sizes, int n_in,
                              void* d_out, int out_size)
{
    const float* x = (const float*)d_in[0];
    const float *Wq, *Wk, *Wv, *Wo, *bq, *bk, *bv, *bo;

    if (in_sizes[2] == DM) {
        Wq = (const float*)d_in[1]; bq = (const float*)d_in[2];
        Wk = (const float*)d_in[3]; bk = (const float*)d_in[4];
        Wv = (const float*)d_in[5]; bv = (const float*)d_in[6];
        Wo = (const float*)d_in[7]; bo = (const float*)d_in[8];
    } else {
        Wq = (const float*)d_in[1]; Wk = (const float*)d_in[2];
        Wv = (const float*)d_in[3]; Wo = (const float*)d_in[4];
        bq = (const float*)d_in[5]; bk = (const float*)d_in[6];
        bv = (const float*)d_in[7]; bo = (const float*)d_in[8];
    }
    float* out = (float*)d_out;

    float *q, *k, *v, *att, *xtf, *wtf;
    cudaGetSymbolAddress((void**)&q,   g_q);
    cudaGetSymbolAddress((void**)&k,   g_k);
    cudaGetSymbolAddress((void**)&v,   g_v);
    cudaGetSymbolAddress((void**)&att, g_att);
    cudaGetSymbolAddress((void**)&xtf, g_xtf);
    cudaGetSymbolAddress((void**)&wtf, g_wtf);

    cudaFuncSetAttribute(gemm_tf32_bias<true>,
                         cudaFuncAttributeMaxDynamicSharedMemorySize,
                         GEMM_SMEM_BYTES);
    cudaFuncSetAttribute(gemm_tf32_bias<false>,
                         cudaFuncAttributeMaxDynamicSharedMemorySize,
                         GEMM_SMEM_BYTES);
    cudaFuncSetAttribute(attn_tc,
                         cudaFuncAttributeMaxDynamicSharedMemorySize,
                         ATT_SMEM_BYTES);

    // Pre-round x and weights to tf32 (bit-identical to mainloop cvt.rna).
    round_x_kernel<<<SEQ * DM / 4 / 256, 256>>>(x, xtf);
    dim3 gw(DM * DM / 4 / 256, 1, 4);
    round_w_kernel<<<gw, 256>>>(Wq, Wk, Wv, Wo, wtf);

    const float* wq = wtf;
    const float* wk = wtf + (size_t)DM * DM;
    const float* wv = wtf + (size_t)2 * DM * DM;
    const float* wo = wtf + (size_t)3 * DM * DM;

    dim3 gqkv(DM / GBN, SEQ / GBM, 3);
    gemm_tf32_bias<true><<<gqkv, 256, GEMM_SMEM_BYTES>>>(
        xtf, wq, wk, wv, bq, bk, bv, q, k, v, SEQ, DM, DM);

    dim3 gat(SEQ / QT, NH);
    attn_tc<<<gat, 256, ATT_SMEM_BYTES>>>();

    dim3 gout(DM / GBN, SEQ / GBM, 1);
    gemm_tf32_bias<false><<<gout, 256, GEMM_SMEM_BYTES>>>(
        att, wo, wo, wo, bo, bo, bo, out, out, out, SEQ, DM, DM);
}

// round 12
// speedup vs baseline: 3.3571x; 1.0145x over previous
#include <cuda_runtime.h>
#include <cstdint>

#define SEQ   4096
#define DM    1024
#define NH    16
#define HD    64
#define WIN   256

// Scratch (allocation-free: __device__ globals)
__device__ float g_q[SEQ * DM];
__device__ float g_k[SEQ * DM];
__device__ float g_v[SEQ * DM];
__device__ float g_att[SEQ * DM];
__device__ float g_xtf[SEQ * DM];        // x pre-rounded to tf32
__device__ float g_wtf[4 * DM * DM];     // Wq,Wk,Wv,Wo pre-rounded to tf32

// ---------------------------------------------------------------------------
// Common helpers
// ---------------------------------------------------------------------------
__device__ __forceinline__ uint32_t f2tf(float f) {
    uint32_t u;
    asm("cvt.rna.tf32.f32 %0, %1;" : "=r"(u) : "f"(f));
    return u;
}

__device__ __forceinline__ void mma_tf32(float (&d)[4],
                                         const uint32_t (&a)[4],
                                         const uint32_t (&b)[2]) {
    asm volatile(
        "mma.sync.aligned.m16n8k8.row.col.f32.tf32.tf32.f32 "
        "{%0,%1,%2,%3}, {%4,%5,%6,%7}, {%8,%9}, {%0,%1,%2,%3};\n"
        : "+f"(d[0]), "+f"(d[1]), "+f"(d[2]), "+f"(d[3])
        : "r"(a[0]), "r"(a[1]), "r"(a[2]), "r"(a[3]),
          "r"(b[0]), "r"(b[1]));
}

__device__ __forceinline__ void cp16(void* sdst, const float* gsrc) {
    uint32_t s = (uint32_t)__cvta_generic_to_shared(sdst);
    asm volatile("cp.async.cg.shared.global [%0], [%1], 16;\n"
                 :: "r"(s), "l"(gsrc));
}
__device__ __forceinline__ void cp_commit() {
    asm volatile("cp.async.commit_group;\n");
}
template <int N> __device__ __forceinline__ void cp_wait() {
    asm volatile("cp.async.wait_group %0;\n" :: "n"(N));
}

// ---------------------------------------------------------------------------
// tf32 pre-rounding kernels (cvt.rna once in GMEM, removed from mainloops).
// ---------------------------------------------------------------------------
__global__ __launch_bounds__(256)
void round_x_kernel(const float* __restrict__ src, float* __restrict__ dst)
{
    int i = blockIdx.x * 256 + threadIdx.x;   // n4 = SEQ*DM/4
    float4 v = ((const float4*)src)[i];
    uint4 w;
    w.x = f2tf(v.x); w.y = f2tf(v.y); w.z = f2tf(v.z); w.w = f2tf(v.w);
    ((uint4*)dst)[i] = w;
}

__global__ __launch_bounds__(256)
void round_w_kernel(const float* __restrict__ W0, const float* __restrict__ W1,
                    const float* __restrict__ W2, const float* __restrict__ W3,
                    float* __restrict__ dst)
{
    const float* W = (blockIdx.z == 0) ? W0 : (blockIdx.z == 1) ? W1
                   : (blockIdx.z == 2) ? W2 : W3;
    int i = blockIdx.x * 256 + threadIdx.x;   // n4 = DM*DM/4
    float4 v = ((const float4*)W)[i];
    uint4 w;
    w.x = f2tf(v.x); w.y = f2tf(v.y); w.z = f2tf(v.z); w.w = f2tf(v.w);
    ((uint4*)(dst + (size_t)blockIdx.z * DM * DM))[i] = w;
}

// ---------------------------------------------------------------------------
// tf32 tensor-core GEMM with bias, 3-stage cp.async pipeline (R9 verified).
// ---------------------------------------------------------------------------
#define GBM 128
#define GBN 128
#define GBK 32
#define SAW 36
#define SBW 136
#define ASZ (GBM * SAW)
#define BSZ (GBK * SBW)
#define GSTAGES 3
#define GEMM_SMEM_BYTES (GSTAGES * (ASZ + BSZ) * 4)   // 107520

template <bool ROUND_C>
__global__ __launch_bounds__(256, 2)
void gemm_tf32_bias(const float* __restrict__ A,
                    const float* __restrict__ B0, const float* __restrict__ B1,
                    const float* __restrict__ B2,
                    const float* __restrict__ b0, const float* __restrict__ b1,
                    const float* __restrict__ b2,
                    float* __restrict__ C0, float* __restrict__ C1,
                    float* __restrict__ C2,
                    int M, int N, int K)
{
    const float* B    = (blockIdx.z == 0) ? B0 : ((blockIdx.z == 1) ? B1 : B2);
    const float* bias = (blockIdx.z == 0) ? b0 : ((blockIdx.z == 1) ? b1 : b2);
    float*       C    = (blockIdx.z == 0) ? C0 : ((blockIdx.z == 1) ? C1 : C2);

    extern __shared__ float smg[];
    float* SAbase = smg;
    float* SBbase = smg + GSTAGES * ASZ;

    const int tid  = threadIdx.x;
    const int wid  = tid >> 5;
    const int lane = tid & 31;
    const int wm   = wid & 1;
    const int wn   = wid >> 1;
    const int gid  = lane >> 2;
    const int tig  = lane & 3;

    const float* Aptr = A + (long)blockIdx.y * GBM * K;
    const float* Bptr = B + blockIdx.x * GBN;

    const int arow = tid >> 3;
    const int ac   = (tid & 7) * 4;
    const int brow = tid >> 5;
    const int bc   = (tid & 31) * 4;

    float acc[4][4][4];
#pragma unroll
    for (int mi = 0; mi < 4; mi++)
#pragma unroll
        for (int ni = 0; ni < 4; ni++)
#pragma unroll
            for (int r = 0; r < 4; r++) acc[mi][ni][r] = 0.f;

    const int NT = K / GBK;

#define GEMM_ISSUE(KT, S)                                                     \
    do {                                                                      \
        float* as_ = SAbase + (S) * ASZ;                                      \
        float* bs_ = SBbase + (S) * BSZ;                                      \
        _Pragma("unroll")                                                     \
        for (int i_ = 0; i_ < 4; i_++) {                                      \
            int r_ = arow + i_ * 32;                                          \
            cp16(as_ + r_ * SAW + ac,                                         \
                 Aptr + (long)r_ * K + (KT) * GBK + ac);                      \
        }                                                                     \
        _Pragma("unroll")                                                     \
        for (int i_ = 0; i_ < 4; i_++) {                                      \
            int r_ = brow + i_ * 8;                                           \
            cp16(bs_ + r_ * SBW + bc,                                         \
                 Bptr + (long)((KT) * GBK + r_) * N + bc);                    \
        }                                                                     \
    } while (0)

#define LOAD_FRAGS(BUF, KB)                                                   \
    do {                                                                      \
        _Pragma("unroll")                                                     \
        for (int mi = 0; mi < 4; mi++) {                                      \
            int m = wm * 64 + mi * 16 + gid;                                  \
            af[BUF][mi][0] = asu[(m)     * SAW + (KB) + tig];                 \
            af[BUF][mi][1] = asu[(m + 8) * SAW + (KB) + tig];                 \
            af[BUF][mi][2] = asu[(m)     * SAW + (KB) + tig + 4];             \
            af[BUF][mi][3] = asu[(m + 8) * SAW + (KB) + tig + 4];             \
        }                                                                     \
        _Pragma("unroll")                                                     \
        for (int ni = 0; ni < 4; ni++) {                                      \
            int n = wn * 32 + ni * 8 + gid;                                   \
            bf[BUF][ni][0] = bsu[((KB) + tig)     * SBW + n];                 \
            bf[BUF][ni][1] = bsu[((KB) + tig + 4) * SBW + n];                 \
        }                                                                     \
    } while (0)

    GEMM_ISSUE(0, 0); cp_commit();
    GEMM_ISSUE(1, 1); cp_commit();

    for (int kt = 0; kt < NT; kt++) {
        const int s = kt % GSTAGES;
        if (kt + 2 < NT) cp_wait<1>(); else cp_wait<0>();
        __syncthreads();
        if (kt + 2 < NT) { GEMM_ISSUE(kt + 2, (kt + 2) % GSTAGES); cp_commit(); }

        const uint32_t* asu = (const uint32_t*)(SAbase + s * ASZ);
        const uint32_t* bsu = (const uint32_t*)(SBbase + s * BSZ);

        uint32_t af[2][4][4], bf[2][4][2];
        LOAD_FRAGS(0, 0);
#pragma unroll
        for (int ks = 0; ks < 4; ks++) {
            const int cur = ks & 1;
            if (ks < 3) {
                const int nxt = cur ^ 1;
                LOAD_FRAGS(nxt, (ks + 1) * 8);
            }
#pragma unroll
            for (int mi = 0; mi < 4; mi++)
#pragma unroll
                for (int ni = 0; ni < 4; ni++)
                    mma_tf32(acc[mi][ni], af[cur][mi], bf[cur][ni]);
        }
    }
#undef GEMM_ISSUE
#undef LOAD_FRAGS

    const int row_base = blockIdx.y * GBM + wm * 64;
    const int col_base = blockIdx.x * GBN + wn * 32;
#pragma unroll
    for (int mi = 0; mi < 4; mi++) {
#pragma unroll
        for (int ni = 0; ni < 4; ni++) {
            int r0 = row_base + mi * 16 + gid;
            int c  = col_base + ni * 8 + 2 * tig;
            float2 bv = *(const float2*)&bias[c];
            float2 o01, o23;
            o01.x = acc[mi][ni][0] + bv.x;
            o01.y = acc[mi][ni][1] + bv.y;
            o23.x = acc[mi][ni][2] + bv.x;
            o23.y = acc[mi][ni][3] + bv.y;
            if (ROUND_C) {
                o01.x = __uint_as_float(f2tf(o01.x));
                o01.y = __uint_as_float(f2tf(o01.y));
                o23.x = __uint_as_float(f2tf(o23.x));
                o23.y = __uint_as_float(f2tf(o23.y));
            }
            *(float2*)&C[(long)r0 * N + c]       = o01;
            *(float2*)&C[(long)(r0 + 8) * N + c] = o23;
        }
    }
}

// ---------------------------------------------------------------------------
// Tensor-core sliding-window flash attention, cp.async double-buffered K/V.
// K stays NATURAL [key][d] with stride 68: S b-frag addr (n*68 + k) mod 32 =
// 4*gid + tig -> conflict-free. V natural [key][d] stride 72 (8*tig + gid ->
// conflict-free). Staging: 64 rows x 16 chunks of 16B; 256 threads, 4 threads
// per row, each thread copies 4 chunks (cols sc4 + 16j) per tensor per tile.
// Loads for tile kt+2 issue after all warps finish reading stage s.
// Math stream is bit-identical to the R9 passing kernel.
// ---------------------------------------------------------------------------
#define QT    128
#define SQ_   68
#define SK_   68
#define SV_   72
#define KSZ   (64 * SK_)
#define VSZ   (64 * SV_)
#define ATT_SMEM_BYTES ((2 * QT * SQ_ + 2 * KSZ + 2 * VSZ) * 4)   // 141312

__global__ __launch_bounds__(256, 1)
void attn_tc()
{
    extern __shared__ float sma[];
    uint32_t* Qs = (uint32_t*)sma;                 // [128][68] tf32 (scaled)
    uint32_t* Ps = Qs + QT * SQ_;                  // [128][68] tf32
    float*    Ks = sma + 2 * QT * SQ_;             // 2 x [64 key][68]
    float*    Vs = Ks + 2 * KSZ;                   // 2 x [64 key][72]

    const int h    = blockIdx.y;
    const int qt   = blockIdx.x;
    const int q0   = qt * QT;
    const int tid  = threadIdx.x;
    const int wid  = tid >> 5;
    const int lane = tid & 31;
    const int gid  = lane >> 2;
    const int tig  = lane & 3;
    const int col  = h * HD;
    const int qw   = wid * 16;

    const int srow = tid >> 2;            // 0..63  (staging row = key)
    const int sc4  = (tid & 3) * 4;       // base col chunk; +16j covers row

    int kt_lo = 2 * qt - 4; if (kt_lo < 0) kt_lo = 0;
    const int kt_hi = 2 * qt + 1;

#define ATT_STAGE(KT, S)                                                      \
    do {                                                                      \
        long gb_ = (long)((KT) * 64 + srow) * DM + col;                       \
        float* kd_ = Ks + (S) * KSZ + srow * SK_;                             \
        float* vd_ = Vs + (S) * VSZ + srow * SV_;                             \
        _Pragma("unroll")                                                     \
        for (int j_ = 0; j_ < 4; j_++) {                                      \
            int c_ = sc4 + 16 * j_;                                           \
            cp16(kd_ + c_, &g_k[gb_ + c_]);                                   \
            cp16(vd_ + c_, &g_v[gb_ + c_]);                                   \
        }                                                                     \
    } while (0)

    // Prefetch first two tiles (window always spans >= 2 tiles).
    ATT_STAGE(kt_lo, 0);     cp_commit();
    ATT_STAGE(kt_lo + 1, 1); cp_commit();

    // Load + scale Q tile (overlaps with the in-flight K/V copies).
    for (int i = tid; i < QT * 16; i += 256) {
        int row = i >> 4;
        int c4  = (i & 15) * 4;
        float4 v = *(const float4*)&g_q[(long)(q0 + row) * DM + col + c4];
        uint32_t* dst = &Qs[row * SQ_ + c4];
        dst[0] = __float_as_uint(v.x * 0.125f);   // exact: q already tf32
        dst[1] = __float_as_uint(v.y * 0.125f);
        dst[2] = __float_as_uint(v.z * 0.125f);
        dst[3] = __float_as_uint(v.w * 0.125f);
    }

    const int prow0 = (qw + gid) * SQ_;
    const int prow1 = (qw + gid + 8) * SQ_;

    float m0 = -1e30f, m1 = -1e30f, l0 = 0.f, l1 = 0.f;
    float o[8][4];
#pragma unroll
    for (int ni = 0; ni < 8; ni++)
#pragma unroll
        for (int r = 0; r < 4; r++) o[ni][r] = 0.f;

    for (int kt = kt_lo; kt <= kt_hi; kt++) {
        const int s = (kt - kt_lo) & 1;
        if (kt + 1 <= kt_hi) cp_wait<1>(); else cp_wait<0>();
        __syncthreads();   // stage s data visible to all warps (covers Qs too)

        const uint32_t* ks = (const uint32_t*)(Ks + s * KSZ);
        const uint32_t* vs = (const uint32_t*)(Vs + s * VSZ);

        // S = Q @ K^T  (K natural layout: element (k,n) at ks[n*SK_ + k])
        float sr[8][4];
#pragma unroll
        for (int ni = 0; ni < 8; ni++)
#pragma unroll
            for (int r = 0; r < 4; r++) sr[ni][r] = 0.f;

#pragma unroll
        for (int ksl = 0; ksl < 8; ksl++) {
            const int kb = ksl * 8;
            uint32_t a[4];
            a[0] = Qs[prow0 + kb + tig];
            a[1] = Qs[prow1 + kb + tig];
            a[2] = Qs[prow0 + kb + tig + 4];
            a[3] = Qs[prow1 + kb + tig + 4];
            uint32_t b[8][2];
#pragma unroll
            for (int ni = 0; ni < 8; ni++) {
                int n = ni * 8 + gid;
                b[ni][0] = ks[n * SK_ + kb + tig];
                b[ni][1] = ks[n * SK_ + kb + tig + 4];
            }
#pragma unroll
            for (int ni = 0; ni < 8; ni++) mma_tf32(sr[ni], a, b[ni]);
        }

        // Mask + row stats.
        const int iq0 = q0 + qw + gid;
        const int iq1 = iq0 + 8;
        float tmax0 = -1e30f, tmax1 = -1e30f;
#pragma unroll
        for (int ni = 0; ni < 8; ni++) {
            int jg = kt * 64 + ni * 8 + 2 * tig;
            bool k0, k1;
            k0 = (jg     <= iq0) && (iq0 - jg     < WIN);
            k1 = (jg + 1 <= iq0) && (iq0 - jg - 1 < WIN);
            sr[ni][0] = k0 ? sr[ni][0] : -1e30f;
            sr[ni][1] = k1 ? sr[ni][1] : -1e30f;
            k0 = (jg     <= iq1) && (iq1 - jg     < WIN);
            k1 = (jg + 1 <= iq1) && (iq1 - jg - 1 < WIN);
            sr[ni][2] = k0 ? sr[ni][2] : -1e30f;
            sr[ni][3] = k1 ? sr[ni][3] : -1e30f;
            tmax0 = fmaxf(tmax0, fmaxf(sr[ni][0], sr[ni][1]));
            tmax1 = fmaxf(tmax1, fmaxf(sr[ni][2], sr[ni][3]));
        }
        tmax0 = fmaxf(tmax0, __shfl_xor_sync(0xffffffffu, tmax0, 1));
        tmax0 = fmaxf(tmax0, __shfl_xor_sync(0xffffffffu, tmax0, 2));
        tmax1 = fmaxf(tmax1, __shfl_xor_sync(0xffffffffu, tmax1, 1));
        tmax1 = fmaxf(tmax1, __shfl_xor_sync(0xffffffffu, tmax1, 2));

        float mn0 = fmaxf(m0, tmax0), mn1 = fmaxf(m1, tmax1);
        float corr0 = __expf(m0 - mn0), corr1 = __expf(m1 - mn1);
        m0 = mn0; m1 = mn1;

        float ls0 = 0.f, ls1 = 0.f;
#pragma unroll
        for (int ni = 0; ni < 8; ni++) {
            int c = ni * 8 + 2 * tig;
            float p0 = (sr[ni][0] > -1e29f) ? __expf(sr[ni][0] - m0) : 0.f;
            float p1 = (sr[ni][1] > -1e29f) ? __expf(sr[ni][1] - m0) : 0.f;
            float p2 = (sr[ni][2] > -1e29f) ? __expf(sr[ni][2] - m1) : 0.f;
            float p3 = (sr[ni][3] > -1e29f) ? __expf(sr[ni][3] - m1) : 0.f;
            Ps[prow0 + c]     = f2tf(p0);
            Ps[prow0 + c + 1] = f2tf(p1);
            Ps[prow1 + c]     = f2tf(p2);
            Ps[prow1 + c + 1] = f2tf(p3);
            ls0 += p0 + p1;
            ls1 += p2 + p3;
        }
        ls0 += __shfl_xor_sync(0xffffffffu, ls0, 1);
        ls0 += __shfl_xor_sync(0xffffffffu, ls0, 2);
        ls1 += __shfl_xor_sync(0xffffffffu, ls1, 1);
        ls1 += __shfl_xor_sync(0xffffffffu, ls1, 2);
        l0 = l0 * corr0 + ls0;
        l1 = l1 * corr1 + ls1;
#pragma unroll
        for (int ni = 0; ni < 8; ni++) {
            o[ni][0] *= corr0; o[ni][1] *= corr0;
            o[ni][2] *= corr1; o[ni][3] *= corr1;
        }

        __syncwarp();   // Ps rows are per-warp private

        // O += P @ V  (V natural: element (k,n) at vs[k*SV_ + n])
#pragma unroll
        for (int ksl = 0; ksl < 8; ksl++) {
            const int kb = ksl * 8;
            uint32_t a[4];
            a[0] = Ps[prow0 + kb + tig];
            a[1] = Ps[prow1 + kb + tig];
            a[2] = Ps[prow0 + kb + tig + 4];
            a[3] = Ps[prow1 + kb + tig + 4];
            uint32_t b[8][2];
#pragma unroll
            for (int ni = 0; ni < 8; ni++) {
                int n = ni * 8 + gid;
                b[ni][0] = vs[(kb + tig) * SV_ + n];
                b[ni][1] = vs[(kb + tig + 4) * SV_ + n];
            }
#pragma unroll
            for (int ni = 0; ni < 8; ni++) mma_tf32(o[ni], a, b[ni]);
        }

        __syncthreads();   // all warps done reading stage s
        if (kt + 2 <= kt_hi) { ATT_STAGE(kt + 2, s); cp_commit(); }
    }
#undef ATT_STAGE

    // Epilogue: normalize, round to tf32 (consumer is the tf32 Wo GEMM).
    const float inv0 = 1.f / l0, inv1 = 1.f / l1;
    const int r0 = q0 + qw + gid;
#pragma unroll
    for (int ni = 0; ni < 8; ni++) {
        int c = col + ni * 8 + 2 * tig;
        float2 w0, w1;
        w0.x = __uint_as_float(f2tf(o[ni][0] * inv0));
        w0.y = __uint_as_float(f2tf(o[ni][1] * inv0));
        w1.x = __uint_as_float(f2tf(o[ni][2] * inv1));
        w1.y = __uint_as_float(f2tf(o[ni][3] * inv1));
        *(float2*)&g_att[(long)r0 * DM + c]       = w0;
        *(float2*)&g_att[(long)(r0 + 8) * DM + c] = w1;
    }
}

// ---------------------------------------------------------------------------
// Launch. Input order resolved at runtime from in_sizes (weights DM*DM,
// biases DM): grouped setup_inputs order or interleaved pair order.
// ---------------------------------------------------------------------------
extern "C" void kernel_launch(void* const* d_in, const int* in_sizes, int n_in,
                              void* d_out, int out_size)
{
    const float* x = (const float*)d_in[0];
    const float *Wq, *Wk, *Wv, *Wo, *bq, *bk, *bv, *bo;

    if (in_sizes[2] == DM) {
        Wq = (const float*)d_in[1]; bq = (const float*)d_in[2];
        Wk = (const float*)d_in[3]; bk = (const float*)d_in[4];
        Wv = (const float*)d_in[5]; bv = (const float*)d_in[6];
        Wo = (const float*)d_in[7]; bo = (const float*)d_in[8];
    } else {
        Wq = (const float*)d_in[1]; Wk = (const float*)d_in[2];
        Wv = (const float*)d_in[3]; Wo = (const float*)d_in[4];
        bq = (const float*)d_in[5]; bk = (const float*)d_in[6];
        bv = (const float*)d_in[7]; bo = (const float*)d_in[8];
    }
    float* out = (float*)d_out;

    float *q, *k, *v, *att, *xtf, *wtf;
    cudaGetSymbolAddress((void**)&q,   g_q);
    cudaGetSymbolAddress((void**)&k,   g_k);
    cudaGetSymbolAddress((void**)&v,   g_v);
    cudaGetSymbolAddress((void**)&att, g_att);
    cudaGetSymbolAddress((void**)&xtf, g_xtf);
    cudaGetSymbolAddress((void**)&wtf, g_wtf);

    cudaFuncSetAttribute(gemm_tf32_bias<true>,
                         cudaFuncAttributeMaxDynamicSharedMemorySize,
                         GEMM_SMEM_BYTES);
    cudaFuncSetAttribute(gemm_tf32_bias<false>,
                         cudaFuncAttributeMaxDynamicSharedMemorySize,
                         GEMM_SMEM_BYTES);
    cudaFuncSetAttribute(attn_tc,
                         cudaFuncAttributeMaxDynamicSharedMemorySize,
                         ATT_SMEM_BYTES);

    // Pre-round x and weights to tf32 (bit-identical to mainloop cvt.rna).
    round_x_kernel<<<SEQ * DM / 4 / 256, 256>>>(x, xtf);
    dim3 gw(DM * DM / 4 / 256, 1, 4);
    round_w_kernel<<<gw, 256>>>(Wq, Wk, Wv, Wo, wtf);

    const float* wq = wtf;
    const float* wk = wtf + (size_t)DM * DM;
    const float* wv = wtf + (size_t)2 * DM * DM;
    const float* wo = wtf + (size_t)3 * DM * DM;

    dim3 gqkv(DM / GBN, SEQ / GBM, 3);
    gemm_tf32_bias<true><<<gqkv, 256, GEMM_SMEM_BYTES>>>(
        xtf, wq, wk, wv, bq, bk, bv, q, k, v, SEQ, DM, DM);

    dim3 gat(SEQ / QT, NH);
    attn_tc<<<gat, 256, ATT_SMEM_BYTES>>>();

    dim3 gout(DM / GBN, SEQ / GBM, 1);
    gemm_tf32_bias<false><<<gout, 256, GEMM_SMEM_BYTES>>>(
        att, wo, wo, wo, bo, bo, bo, out, out, out, SEQ, DM, DM);
}

// round 13
// speedup vs baseline: 3.4601x; 1.0307x over previous
#include <cuda_runtime.h>
#include <cstdint>

#define SEQ   4096
#define DM    1024
#define NH    16
#define HD    64
#define WIN   256

// Scratch (allocation-free: __device__ globals)
__device__ float g_q[SEQ * DM];
__device__ float g_k[SEQ * DM];
__device__ float g_v[SEQ * DM];
__device__ float g_att[SEQ * DM];
__device__ float g_xtf[SEQ * DM];        // x pre-rounded to tf32
__device__ float g_wtf[4 * DM * DM];     // Wq,Wk,Wv,Wo pre-rounded to tf32

// ---------------------------------------------------------------------------
// Common helpers
// ---------------------------------------------------------------------------
__device__ __forceinline__ uint32_t f2tf(float f) {
    uint32_t u;
    asm("cvt.rna.tf32.f32 %0, %1;" : "=r"(u) : "f"(f));
    return u;
}

__device__ __forceinline__ void mma_tf32(float (&d)[4],
                                         const uint32_t (&a)[4],
                                         const uint32_t (&b)[2]) {
    asm volatile(
        "mma.sync.aligned.m16n8k8.row.col.f32.tf32.tf32.f32 "
        "{%0,%1,%2,%3}, {%4,%5,%6,%7}, {%8,%9}, {%0,%1,%2,%3};\n"
        : "+f"(d[0]), "+f"(d[1]), "+f"(d[2]), "+f"(d[3])
        : "r"(a[0]), "r"(a[1]), "r"(a[2]), "r"(a[3]),
          "r"(b[0]), "r"(b[1]));
}

__device__ __forceinline__ void cp16(void* sdst, const float* gsrc) {
    uint32_t s = (uint32_t)__cvta_generic_to_shared(sdst);
    asm volatile("cp.async.cg.shared.global [%0], [%1], 16;\n"
                 :: "r"(s), "l"(gsrc));
}
__device__ __forceinline__ void cp_commit() {
    asm volatile("cp.async.commit_group;\n");
}
template <int N> __device__ __forceinline__ void cp_wait() {
    asm volatile("cp.async.wait_group %0;\n" :: "n"(N));
}

// ---------------------------------------------------------------------------
// tf32 pre-rounding kernels (cvt.rna once in GMEM, removed from mainloops).
// ---------------------------------------------------------------------------
__global__ __launch_bounds__(256)
void round_x_kernel(const float* __restrict__ src, float* __restrict__ dst)
{
    int i = blockIdx.x * 256 + threadIdx.x;   // n4 = SEQ*DM/4
    float4 v = ((const float4*)src)[i];
    uint4 w;
    w.x = f2tf(v.x); w.y = f2tf(v.y); w.z = f2tf(v.z); w.w = f2tf(v.w);
    ((uint4*)dst)[i] = w;
}

__global__ __launch_bounds__(256)
void round_w_kernel(const float* __restrict__ W0, const float* __restrict__ W1,
                    const float* __restrict__ W2, const float* __restrict__ W3,
                    float* __restrict__ dst)
{
    const float* W = (blockIdx.z == 0) ? W0 : (blockIdx.z == 1) ? W1
                   : (blockIdx.z == 2) ? W2 : W3;
    int i = blockIdx.x * 256 + threadIdx.x;   // n4 = DM*DM/4
    float4 v = ((const float4*)W)[i];
    uint4 w;
    w.x = f2tf(v.x); w.y = f2tf(v.y); w.z = f2tf(v.z); w.w = f2tf(v.w);
    ((uint4*)(dst + (size_t)blockIdx.z * DM * DM))[i] = w;
}

// ---------------------------------------------------------------------------
// tf32 tensor-core GEMM with bias, 3-stage cp.async pipeline (verified).
// ---------------------------------------------------------------------------
#define GBM 128
#define GBN 128
#define GBK 32
#define SAW 36
#define SBW 136
#define ASZ (GBM * SAW)
#define BSZ (GBK * SBW)
#define GSTAGES 3
#define GEMM_SMEM_BYTES (GSTAGES * (ASZ + BSZ) * 4)   // 107520

template <bool ROUND_C>
__global__ __launch_bounds__(256, 2)
void gemm_tf32_bias(const float* __restrict__ A,
                    const float* __restrict__ B0, const float* __restrict__ B1,
                    const float* __restrict__ B2,
                    const float* __restrict__ b0, const float* __restrict__ b1,
                    const float* __restrict__ b2,
                    float* __restrict__ C0, float* __restrict__ C1,
                    float* __restrict__ C2,
                    int M, int N, int K)
{
    const float* B    = (blockIdx.z == 0) ? B0 : ((blockIdx.z == 1) ? B1 : B2);
    const float* bias = (blockIdx.z == 0) ? b0 : ((blockIdx.z == 1) ? b1 : b2);
    float*       C    = (blockIdx.z == 0) ? C0 : ((blockIdx.z == 1) ? C1 : C2);

    extern __shared__ float smg[];
    float* SAbase = smg;
    float* SBbase = smg + GSTAGES * ASZ;

    const int tid  = threadIdx.x;
    const int wid  = tid >> 5;
    const int lane = tid & 31;
    const int wm   = wid & 1;
    const int wn   = wid >> 1;
    const int gid  = lane >> 2;
    const int tig  = lane & 3;

    const float* Aptr = A + (long)blockIdx.y * GBM * K;
    const float* Bptr = B + blockIdx.x * GBN;

    const int arow = tid >> 3;
    const int ac   = (tid & 7) * 4;
    const int brow = tid >> 5;
    const int bc   = (tid & 31) * 4;

    float acc[4][4][4];
#pragma unroll
    for (int mi = 0; mi < 4; mi++)
#pragma unroll
        for (int ni = 0; ni < 4; ni++)
#pragma unroll
            for (int r = 0; r < 4; r++) acc[mi][ni][r] = 0.f;

    const int NT = K / GBK;

#define GEMM_ISSUE(KT, S)                                                     \
    do {                                                                      \
        float* as_ = SAbase + (S) * ASZ;                                      \
        float* bs_ = SBbase + (S) * BSZ;                                      \
        _Pragma("unroll")                                                     \
        for (int i_ = 0; i_ < 4; i_++) {                                      \
            int r_ = arow + i_ * 32;                                          \
            cp16(as_ + r_ * SAW + ac,                                         \
                 Aptr + (long)r_ * K + (KT) * GBK + ac);                      \
        }                                                                     \
        _Pragma("unroll")                                                     \
        for (int i_ = 0; i_ < 4; i_++) {                                      \
            int r_ = brow + i_ * 8;                                           \
            cp16(bs_ + r_ * SBW + bc,                                         \
                 Bptr + (long)((KT) * GBK + r_) * N + bc);                    \
        }                                                                     \
    } while (0)

#define LOAD_FRAGS(BUF, KB)                                                   \
    do {                                                                      \
        _Pragma("unroll")                                                     \
        for (int mi = 0; mi < 4; mi++) {                                      \
            int m = wm * 64 + mi * 16 + gid;                                  \
            af[BUF][mi][0] = asu[(m)     * SAW + (KB) + tig];                 \
            af[BUF][mi][1] = asu[(m + 8) * SAW + (KB) + tig];                 \
            af[BUF][mi][2] = asu[(m)     * SAW + (KB) + tig + 4];             \
            af[BUF][mi][3] = asu[(m + 8) * SAW + (KB) + tig + 4];             \
        }                                                                     \
        _Pragma("unroll")                                                     \
        for (int ni = 0; ni < 4; ni++) {                                      \
            int n = wn * 32 + ni * 8 + gid;                                   \
            bf[BUF][ni][0] = bsu[((KB) + tig)     * SBW + n];                 \
            bf[BUF][ni][1] = bsu[((KB) + tig + 4) * SBW + n];                 \
        }                                                                     \
    } while (0)

    GEMM_ISSUE(0, 0); cp_commit();
    GEMM_ISSUE(1, 1); cp_commit();

    for (int kt = 0; kt < NT; kt++) {
        const int s = kt % GSTAGES;
        if (kt + 2 < NT) cp_wait<1>(); else cp_wait<0>();
        __syncthreads();
        if (kt + 2 < NT) { GEMM_ISSUE(kt + 2, (kt + 2) % GSTAGES); cp_commit(); }

        const uint32_t* asu = (const uint32_t*)(SAbase + s * ASZ);
        const uint32_t* bsu = (const uint32_t*)(SBbase + s * BSZ);

        uint32_t af[2][4][4], bf[2][4][2];
        LOAD_FRAGS(0, 0);
#pragma unroll
        for (int ks = 0; ks < 4; ks++) {
            const int cur = ks & 1;
            if (ks < 3) {
                const int nxt = cur ^ 1;
                LOAD_FRAGS(nxt, (ks + 1) * 8);
            }
#pragma unroll
            for (int mi = 0; mi < 4; mi++)
#pragma unroll
                for (int ni = 0; ni < 4; ni++)
                    mma_tf32(acc[mi][ni], af[cur][mi], bf[cur][ni]);
        }
    }
#undef GEMM_ISSUE
#undef LOAD_FRAGS

    const int row_base = blockIdx.y * GBM + wm * 64;
    const int col_base = blockIdx.x * GBN + wn * 32;
#pragma unroll
    for (int mi = 0; mi < 4; mi++) {
#pragma unroll
        for (int ni = 0; ni < 4; ni++) {
            int r0 = row_base + mi * 16 + gid;
            int c  = col_base + ni * 8 + 2 * tig;
            float2 bv = *(const float2*)&bias[c];
            float2 o01, o23;
            o01.x = acc[mi][ni][0] + bv.x;
            o01.y = acc[mi][ni][1] + bv.y;
            o23.x = acc[mi][ni][2] + bv.x;
            o23.y = acc[mi][ni][3] + bv.y;
            if (ROUND_C) {
                o01.x = __uint_as_float(f2tf(o01.x));
                o01.y = __uint_as_float(f2tf(o01.y));
                o23.x = __uint_as_float(f2tf(o23.x));
                o23.y = __uint_as_float(f2tf(o23.y));
            }
            *(float2*)&C[(long)r0 * N + c]       = o01;
            *(float2*)&C[(long)(r0 + 8) * N + c] = o23;
        }
    }
}

// ---------------------------------------------------------------------------
// Tensor-core sliding-window flash attention.
// QT=64 queries per CTA, 128 threads (4 warps x 16 query rows) -> smem
// 106496 B -> 2 CTAs/SM: two desynchronized CTAs overlap softmax (MUFU)
// with MMAs (tensor). Per-query math stream identical to the R12 pass
// (same key-tile set/order, same ops) -> bit-identical output.
// K natural [key][d] stride 68 (b-frag banks 4*gid+tig, conflict-free),
// V natural stride 72. cp.async double-buffered K/V, 8 chunks/thread each.
// ---------------------------------------------------------------------------
#define QT    64
#define ATHR  128
#define SQ_   68
#define SK_   68
#define SV_   72
#define KSZ   (64 * SK_)
#define VSZ   (64 * SV_)
#define ATT_SMEM_BYTES ((2 * QT * SQ_ + 2 * KSZ + 2 * VSZ) * 4)   // 106496

__global__ __launch_bounds__(ATHR, 2)
void attn_tc()
{
    extern __shared__ float sma[];
    uint32_t* Qs = (uint32_t*)sma;                 // [64][68] tf32 (scaled)
    uint32_t* Ps = Qs + QT * SQ_;                  // [64][68] tf32
    float*    Ks = sma + 2 * QT * SQ_;             // 2 x [64 key][68]
    float*    Vs = Ks + 2 * KSZ;                   // 2 x [64 key][72]

    const int h    = blockIdx.y;
    const int qt   = blockIdx.x;
    const int q0   = qt * QT;
    const int tid  = threadIdx.x;
    const int wid  = tid >> 5;                     // 0..3
    const int lane = tid & 31;
    const int gid  = lane >> 2;
    const int tig  = lane & 3;
    const int col  = h * HD;
    const int qw   = wid * 16;

    const int srow = tid >> 1;            // 0..63  (staging row = key)
    const int sc4  = (tid & 1) * 4;       // base col chunk; +8j covers row

    int kt_lo = qt - 4; if (kt_lo < 0) kt_lo = 0;
    const int kt_hi = qt;

#define ATT_STAGE(KT, S)                                                      \
    do {                                                                      \
        long gb_ = (long)((KT) * 64 + srow) * DM + col;                       \
        float* kd_ = Ks + (S) * KSZ + srow * SK_;                             \
        float* vd_ = Vs + (S) * VSZ + srow * SV_;                             \
        _Pragma("unroll")                                                     \
        for (int j_ = 0; j_ < 8; j_++) {                                      \
            int c_ = sc4 + 8 * j_;                                            \
            cp16(kd_ + c_, &g_k[gb_ + c_]);                                   \
            cp16(vd_ + c_, &g_v[gb_ + c_]);                                   \
        }                                                                     \
    } while (0)

    // Prefetch first two tiles (window always spans >= 2 tiles).
    ATT_STAGE(kt_lo, 0);     cp_commit();
    ATT_STAGE(kt_lo + 1, 1); cp_commit();

    // Load + scale Q tile (overlaps with the in-flight K/V copies).
    for (int i = tid; i < QT * 16; i += ATHR) {
        int row = i >> 4;
        int c4  = (i & 15) * 4;
        float4 v = *(const float4*)&g_q[(long)(q0 + row) * DM + col + c4];
        uint32_t* dst = &Qs[row * SQ_ + c4];
        dst[0] = __float_as_uint(v.x * 0.125f);   // exact: q already tf32
        dst[1] = __float_as_uint(v.y * 0.125f);
        dst[2] = __float_as_uint(v.z * 0.125f);
        dst[3] = __float_as_uint(v.w * 0.125f);
    }

    const int prow0 = (qw + gid) * SQ_;
    const int prow1 = (qw + gid + 8) * SQ_;

    float m0 = -1e30f, m1 = -1e30f, l0 = 0.f, l1 = 0.f;
    float o[8][4];
#pragma unroll
    for (int ni = 0; ni < 8; ni++)
#pragma unroll
        for (int r = 0; r < 4; r++) o[ni][r] = 0.f;

    for (int kt = kt_lo; kt <= kt_hi; kt++) {
        const int s = (kt - kt_lo) & 1;
        if (kt + 1 <= kt_hi) cp_wait<1>(); else cp_wait<0>();
        __syncthreads();   // stage s data visible to all warps (covers Qs too)

        const uint32_t* ks = (const uint32_t*)(Ks + s * KSZ);
        const uint32_t* vs = (const uint32_t*)(Vs + s * VSZ);

        // S = Q @ K^T  (K natural layout: element (k,n) at ks[n*SK_ + k])
        float sr[8][4];
#pragma unroll
        for (int ni = 0; ni < 8; ni++)
#pragma unroll
            for (int r = 0; r < 4; r++) sr[ni][r] = 0.f;

#pragma unroll
        for (int ksl = 0; ksl < 8; ksl++) {
            const int kb = ksl * 8;
            uint32_t a[4];
            a[0] = Qs[prow0 + kb + tig];
            a[1] = Qs[prow1 + kb + tig];
            a[2] = Qs[prow0 + kb + tig + 4];
            a[3] = Qs[prow1 + kb + tig + 4];
            uint32_t b[8][2];
#pragma unroll
            for (int ni = 0; ni < 8; ni++) {
                int n = ni * 8 + gid;
                b[ni][0] = ks[n * SK_ + kb + tig];
                b[ni][1] = ks[n * SK_ + kb + tig + 4];
            }
#pragma unroll
            for (int ni = 0; ni < 8; ni++) mma_tf32(sr[ni], a, b[ni]);
        }

        // Mask + row stats.
        const int iq0 = q0 + qw + gid;
        const int iq1 = iq0 + 8;
        float tmax0 = -1e30f, tmax1 = -1e30f;
#pragma unroll
        for (int ni = 0; ni < 8; ni++) {
            int jg = kt * 64 + ni * 8 + 2 * tig;
            bool k0, k1;
            k0 = (jg     <= iq0) && (iq0 - jg     < WIN);
            k1 = (jg + 1 <= iq0) && (iq0 - jg - 1 < WIN);
            sr[ni][0] = k0 ? sr[ni][0] : -1e30f;
            sr[ni][1] = k1 ? sr[ni][1] : -1e30f;
            k0 = (jg     <= iq1) && (iq1 - jg     < WIN);
            k1 = (jg + 1 <= iq1) && (iq1 - jg - 1 < WIN);
            sr[ni][2] = k0 ? sr[ni][2] : -1e30f;
            sr[ni][3] = k1 ? sr[ni][3] : -1e30f;
            tmax0 = fmaxf(tmax0, fmaxf(sr[ni][0], sr[ni][1]));
            tmax1 = fmaxf(tmax1, fmaxf(sr[ni][2], sr[ni][3]));
        }
        tmax0 = fmaxf(tmax0, __shfl_xor_sync(0xffffffffu, tmax0, 1));
        tmax0 = fmaxf(tmax0, __shfl_xor_sync(0xffffffffu, tmax0, 2));
        tmax1 = fmaxf(tmax1, __shfl_xor_sync(0xffffffffu, tmax1, 1));
        tmax1 = fmaxf(tmax1, __shfl_xor_sync(0xffffffffu, tmax1, 2));

        float mn0 = fmaxf(m0, tmax0), mn1 = fmaxf(m1, tmax1);
        float corr0 = __expf(m0 - mn0), corr1 = __expf(m1 - mn1);
        m0 = mn0; m1 = mn1;

        float ls0 = 0.f, ls1 = 0.f;
#pragma unroll
        for (int ni = 0; ni < 8; ni++) {
            int c = ni * 8 + 2 * tig;
            float p0 = (sr[ni][0] > -1e29f) ? __expf(sr[ni][0] - m0) : 0.f;
            float p1 = (sr[ni][1] > -1e29f) ? __expf(sr[ni][1] - m0) : 0.f;
            float p2 = (sr[ni][2] > -1e29f) ? __expf(sr[ni][2] - m1) : 0.f;
            float p3 = (sr[ni][3] > -1e29f) ? __expf(sr[ni][3] - m1) : 0.f;
            Ps[prow0 + c]     = f2tf(p0);
            Ps[prow0 + c + 1] = f2tf(p1);
            Ps[prow1 + c]     = f2tf(p2);
            Ps[prow1 + c + 1] = f2tf(p3);
            ls0 += p0 + p1;
            ls1 += p2 + p3;
        }
        ls0 += __shfl_xor_sync(0xffffffffu, ls0, 1);
        ls0 += __shfl_xor_sync(0xffffffffu, ls0, 2);
        ls1 += __shfl_xor_sync(0xffffffffu, ls1, 1);
        ls1 += __shfl_xor_sync(0xffffffffu, ls1, 2);
        l0 = l0 * corr0 + ls0;
        l1 = l1 * corr1 + ls1;
#pragma unroll
        for (int ni = 0; ni < 8; ni++) {
            o[ni][0] *= corr0; o[ni][1] *= corr0;
            o[ni][2] *= corr1; o[ni][3] *= corr1;
        }

        __syncwarp();   // Ps rows are per-warp private

        // O += P @ V  (V natural: element (k,n) at vs[k*SV_ + n])
#pragma unroll
        for (int ksl = 0; ksl < 8; ksl++) {
            const int kb = ksl * 8;
            uint32_t a[4];
            a[0] = Ps[prow0 + kb + tig];
            a[1] = Ps[prow1 + kb + tig];
            a[2] = Ps[prow0 + kb + tig + 4];
            a[3] = Ps[prow1 + kb + tig + 4];
            uint32_t b[8][2];
#pragma unroll
            for (int ni = 0; ni < 8; ni++) {
                int n = ni * 8 + gid;
                b[ni][0] = vs[(kb + tig) * SV_ + n];
                b[ni][1] = vs[(kb + tig + 4) * SV_ + n];
            }
#pragma unroll
            for (int ni = 0; ni < 8; ni++) mma_tf32(o[ni], a, b[ni]);
        }

        __syncthreads();   // all warps done reading stage s
        if (kt + 2 <= kt_hi) { ATT_STAGE(kt + 2, s); cp_commit(); }
    }
#undef ATT_STAGE

    // Epilogue: normalize, round to tf32 (consumer is the tf32 Wo GEMM).
    const float inv0 = 1.f / l0, inv1 = 1.f / l1;
    const int r0 = q0 + qw + gid;
#pragma unroll
    for (int ni = 0; ni < 8; ni++) {
        int c = col + ni * 8 + 2 * tig;
        float2 w0, w1;
        w0.x = __uint_as_float(f2tf(o[ni][0] * inv0));
        w0.y = __uint_as_float(f2tf(o[ni][1] * inv0));
        w1.x = __uint_as_float(f2tf(o[ni][2] * inv1));
        w1.y = __uint_as_float(f2tf(o[ni][3] * inv1));
        *(float2*)&g_att[(long)r0 * DM + c]       = w0;
        *(float2*)&g_att[(long)(r0 + 8) * DM + c] = w1;
    }
}

// ---------------------------------------------------------------------------
// Launch. Input order resolved at runtime from in_sizes (weights DM*DM,
// biases DM): grouped setup_inputs order or interleaved pair order.
// ---------------------------------------------------------------------------
extern "C" void kernel_launch(void* const* d_in, const int* in_sizes, int n_in,
                              void* d_out, int out_size)
{
    const float* x = (const float*)d_in[0];
    const float *Wq, *Wk, *Wv, *Wo, *bq, *bk, *bv, *bo;

    if (in_sizes[2] == DM) {
        Wq = (const float*)d_in[1]; bq = (const float*)d_in[2];
        Wk = (const float*)d_in[3]; bk = (const float*)d_in[4];
        Wv = (const float*)d_in[5]; bv = (const float*)d_in[6];
        Wo = (const float*)d_in[7]; bo = (const float*)d_in[8];
    } else {
        Wq = (const float*)d_in[1]; Wk = (const float*)d_in[2];
        Wv = (const float*)d_in[3]; Wo = (const float*)d_in[4];
        bq = (const float*)d_in[5]; bk = (const float*)d_in[6];
        bv = (const float*)d_in[7]; bo = (const float*)d_in[8];
    }
    float* out = (float*)d_out;

    float *q, *k, *v, *att, *xtf, *wtf;
    cudaGetSymbolAddress((void**)&q,   g_q);
    cudaGetSymbolAddress((void**)&k,   g_k);
    cudaGetSymbolAddress((void**)&v,   g_v);
    cudaGetSymbolAddress((void**)&att, g_att);
    cudaGetSymbolAddress((void**)&xtf, g_xtf);
    cudaGetSymbolAddress((void**)&wtf, g_wtf);

    cudaFuncSetAttribute(gemm_tf32_bias<true>,
                         cudaFuncAttributeMaxDynamicSharedMemorySize,
                         GEMM_SMEM_BYTES);
    cudaFuncSetAttribute(gemm_tf32_bias<false>,
                         cudaFuncAttributeMaxDynamicSharedMemorySize,
                         GEMM_SMEM_BYTES);
    cudaFuncSetAttribute(attn_tc,
                         cudaFuncAttributeMaxDynamicSharedMemorySize,
                         ATT_SMEM_BYTES);

    // Pre-round x and weights to tf32 (bit-identical to mainloop cvt.rna).
    round_x_kernel<<<SEQ * DM / 4 / 256, 256>>>(x, xtf);
    dim3 gw(DM * DM / 4 / 256, 1, 4);
    round_w_kernel<<<gw, 256>>>(Wq, Wk, Wv, Wo, wtf);

    const float* wq = wtf;
    const float* wk = wtf + (size_t)DM * DM;
    const float* wv = wtf + (size_t)2 * DM * DM;
    const float* wo = wtf + (size_t)3 * DM * DM;

    dim3 gqkv(DM / GBN, SEQ / GBM, 3);
    gemm_tf32_bias<true><<<gqkv, 256, GEMM_SMEM_BYTES>>>(
        xtf, wq, wk, wv, bq, bk, bv, q, k, v, SEQ, DM, DM);

    dim3 gat(SEQ / QT, NH);
    attn_tc<<<gat, ATHR, ATT_SMEM_BYTES>>>();

    dim3 gout(DM / GBN, SEQ / GBM, 1);
    gemm_tf32_bias<false><<<gout, 256, GEMM_SMEM_BYTES>>>(
        att, wo, wo, wo, bo, bo, bo, out, out, out, SEQ, DM, DM);
}